// round 1
// baseline (speedup 1.0000x reference)
#include <cuda_runtime.h>
#include <math.h>

#define NB 4
#define NC 256
#define NH 128
#define NW 128
#define NHW (NH*NW)
#define NINNER 256
#define NHEADS 4
#define NDH 64
#define NS 16
#define NSS 256
#define QT 64

// -------- scratch (static device arrays; no runtime allocation) --------
__device__ float g_t1[NB*NC*NHW];          // 64 MB  depthwise1 out
__device__ float g_qkv[NB*3*NINNER*NHW];   // 192 MB pointwise1 out (q|k|v)
__device__ float g_kp[NB*NINNER*NSS];      // pooled k
__device__ float g_vp[NB*NINNER*NSS];      // pooled v
__device__ float g_av[NB*NINNER*NHW];      // 64 MB  attention out (NCHW, c = d*4+head)
__device__ float g_t2[NB*NINNER*NHW];      // 64 MB  depthwise2 out

// ======================= depthwise 3x3, pad 1 =======================
__global__ void dw3x3(const float* __restrict__ in, const float* __restrict__ wt,
                      float* __restrict__ out) {
  int idx = blockIdx.x*256 + threadIdx.x;
  int x = idx & (NW-1);
  int y = (idx >> 7) & (NH-1);
  int bc = idx >> 14;             // b*C + c
  int c = bc & (NC-1);
  const float* wp = wt + c*9;
  const float* ip = in + (size_t)bc*NHW;
  float s = 0.f;
  #pragma unroll
  for (int dy = -1; dy <= 1; dy++) {
    int yy = y + dy;
    if ((unsigned)yy >= NH) continue;
    #pragma unroll
    for (int dx = -1; dx <= 1; dx++) {
      int xx = x + dx;
      if ((unsigned)xx >= NW) continue;
      s = fmaf(ip[yy*NW+xx], wp[(dy+1)*3 + dx+1], s);
    }
  }
  out[idx] = s;
}

// ======================= pointwise 1x1 as GEMM =======================
// C[b][m][n] = sum_k A[m][k] * B[b][k][n],  N = 16384, tiles 128x128x8
__global__ void __launch_bounds__(256) pw_gemm(const float* __restrict__ A,
                 const float* __restrict__ Bm, float* __restrict__ Cm,
                 int M, int K) {
  __shared__ float As[8*128];
  __shared__ float Bs[8*128];
  const int N = NHW;
  int bz = blockIdx.z;
  int m0 = blockIdx.y*128, n0 = blockIdx.x*128;
  const float* Bb = Bm + (size_t)bz*K*N;
  float* Cb = Cm + (size_t)bz*M*N;
  int tid = threadIdx.x;
  int tx = tid & 15, ty = tid >> 4;
  float acc[8][8];
  #pragma unroll
  for (int i=0;i<8;i++)
    #pragma unroll
    for (int j=0;j<8;j++) acc[i][j]=0.f;

  for (int k0 = 0; k0 < K; k0 += 8) {
    #pragma unroll
    for (int l = 0; l < 4; l++) {
      int e = l*256 + tid;
      int r = e >> 3, c = e & 7;
      As[c*128 + r] = A[(size_t)(m0+r)*K + k0 + c];
      int kk = e >> 7, n = e & 127;
      Bs[kk*128 + n] = Bb[(size_t)(k0+kk)*N + n0 + n];
    }
    __syncthreads();
    #pragma unroll
    for (int kk = 0; kk < 8; kk++) {
      float a[8], b[8];
      *(float4*)&a[0] = *(const float4*)&As[kk*128 + ty*8];
      *(float4*)&a[4] = *(const float4*)&As[kk*128 + ty*8 + 4];
      *(float4*)&b[0] = *(const float4*)&Bs[kk*128 + tx*8];
      *(float4*)&b[4] = *(const float4*)&Bs[kk*128 + tx*8 + 4];
      #pragma unroll
      for (int i=0;i<8;i++)
        #pragma unroll
        for (int j=0;j<8;j++)
          acc[i][j] = fmaf(a[i], b[j], acc[i][j]);
    }
    __syncthreads();
  }
  #pragma unroll
  for (int i=0;i<8;i++) {
    float* cp = Cb + (size_t)(m0+ty*8+i)*N + n0 + tx*8;
    *(float4*)cp     = make_float4(acc[i][0],acc[i][1],acc[i][2],acc[i][3]);
    *(float4*)(cp+4) = make_float4(acc[i][4],acc[i][5],acc[i][6],acc[i][7]);
  }
}

// ======================= 8x8 max pool of k and v =======================
__global__ void pool8(const float* __restrict__ qkv, float* __restrict__ kp,
                      float* __restrict__ vp) {
  int idx = blockIdx.x*256 + threadIdx.x;   // 0..524287
  int which = idx >> 18;                    // 0 = k, 1 = v (262144 each)
  int r = idx & 262143;
  int ow = r & 15, oh = (r >> 4) & 15;
  int c = (r >> 8) & 255;
  int b = r >> 16;
  const float* ip = qkv + ((size_t)(b*768 + (which ? 512 : 256) + c))*NHW
                    + (oh*8)*NW + ow*8;
  float m = -1e30f;
  #pragma unroll
  for (int i=0;i<8;i++)
    #pragma unroll
    for (int j=0;j<8;j++)
      m = fmaxf(m, ip[i*NW+j]);
  if (which) vp[r] = m; else kp[r] = m;
}

// ======================= fused attention =======================
// block: (b, head, tile of 64 consecutive pixels -> same row h, w = w0..w0+63)
#define KSTR 260   // K/V tile stride (pad: conflict-free scalar + aligned float4)
#define SSTR 260   // score tile stride
#define QSTR 68    // q tile stride (float4-aligned)
#define RSTR 68    // rel table stride
#define OSTR 65    // output staging stride

__global__ void __launch_bounds__(256) attn_k(
    const float* __restrict__ qkv, const float* __restrict__ kp,
    const float* __restrict__ vp, const float* __restrict__ relw,
    const float* __restrict__ relh, float* __restrict__ attn_out,
    float* __restrict__ av) {
  extern __shared__ float sm[];
  float* sKV = sm;                     // 64*260 (K, then reused for V)
  float* sS  = sKV + 64*KSTR;          // 64*260 scores -> probs
  float* sQ  = sS + 64*SSTR;           // 64*68
  float* sRH = sQ + 64*QSTR;           // 31*68
  float* sRW = sRH + 31*RSTR;          // 31*68
  float* sGH = sRW + 31*RSTR;          // 64*17
  float* sGW = sGH + 64*17;            // 64*17
  float* sO  = sQ;                     // reuse sQ region for output staging

  const int tid = threadIdx.x;
  const int tile = blockIdx.x;
  const int head = blockIdx.y;
  const int b = blockIdx.z;
  const int i0 = tile*QT;
  const int hq = i0 >> 7;              // all 64 queries share this row
  const int w0 = i0 & (NW-1);
  const int h8 = hq >> 3;

  // ---- load Q (64 queries x 64 dims), channel = d*4 + head ----
  #pragma unroll
  for (int l = 0; l < 16; l++) {
    int e = l*256 + tid;
    int d = e >> 6, qi = e & 63;
    sQ[qi*QSTR + d] = qkv[((size_t)(b*768) + d*NHEADS + head)*NHW + i0 + qi];
  }
  // ---- rel-pos tables (31 x 64) ----
  for (int e = tid; e < 31*64; e += 256) {
    int r = e >> 6, d = e & 63;
    sRH[r*RSTR + d] = relh[e];
    sRW[r*RSTR + d] = relw[e];
  }
  // ---- load K transposed: sKV[d][j] ----
  #pragma unroll
  for (int d = 0; d < 64; d++)
    sKV[d*KSTR + tid] = kp[((size_t)(b*NINNER) + d*NHEADS + head)*NSS + tid];
  __syncthreads();

  // ---- scores: thread tid owns key j = tid, loop queries ----
  #pragma unroll 1
  for (int qc = 0; qc < QT; qc += 16) {
    float acc[16];
    #pragma unroll
    for (int t=0;t<16;t++) acc[t]=0.f;
    #pragma unroll
    for (int d0 = 0; d0 < 64; d0 += 4) {
      float k0v = sKV[(d0+0)*KSTR + tid];
      float k1v = sKV[(d0+1)*KSTR + tid];
      float k2v = sKV[(d0+2)*KSTR + tid];
      float k3v = sKV[(d0+3)*KSTR + tid];
      #pragma unroll
      for (int t=0;t<16;t++) {
        float4 qv = *(const float4*)&sQ[(qc+t)*QSTR + d0];
        acc[t] = fmaf(qv.x,k0v, fmaf(qv.y,k1v, fmaf(qv.z,k2v, fmaf(qv.w,k3v, acc[t]))));
      }
    }
    #pragma unroll
    for (int t=0;t<16;t++) sS[(qc+t)*SSTR + tid] = acc[t];
  }
  __syncthreads();

  // ---- load V into the K buffer; compute gh/gw bias dots ----
  #pragma unroll
  for (int d = 0; d < 64; d++)
    sKV[d*KSTR + tid] = vp[((size_t)(b*NINNER) + d*NHEADS + head)*NSS + tid];
  #pragma unroll
  for (int it = 0; it < 8; it++) {      // 2048 (qi, kk, table) dots
    int e = it*256 + tid;
    int isw = e >> 10;
    int qi = (e & 1023) >> 4;
    int kk = e & 15;
    int row = isw ? (kk - ((w0 + qi) >> 3) + NS - 1) : (kk - h8 + NS - 1);
    const float* tb = (isw ? sRW : sRH) + row*RSTR;
    const float* qr = sQ + qi*QSTR;
    float s = 0.f;
    #pragma unroll
    for (int d0 = 0; d0 < 64; d0 += 4) {
      float4 a = *(const float4*)&qr[d0];
      float4 c4 = *(const float4*)&tb[d0];
      s = fmaf(a.x,c4.x, fmaf(a.y,c4.y, fmaf(a.z,c4.z, fmaf(a.w,c4.w, s))));
    }
    if (isw) sGW[qi*17 + kk] = s; else sGH[qi*17 + kk] = s;
  }
  __syncthreads();

  // ---- bias + scale + softmax: 4 threads per query ----
  {
    const int q = tid >> 2, lane = tid & 3;
    float* srow = sS + q*SSTR;
    const float* ghr = sGH + q*17;
    const float* gwr = sGW + q*17;
    float mx = -1e30f;
    #pragma unroll
    for (int i = 0; i < 64; i++) {
      int j = i*4 + lane;
      float s = (srow[j] + ghr[j >> 4] + gwr[j & 15]) * 0.125f;
      srow[j] = s;
      mx = fmaxf(mx, s);
    }
    mx = fmaxf(mx, __shfl_xor_sync(0xffffffffu, mx, 1));
    mx = fmaxf(mx, __shfl_xor_sync(0xffffffffu, mx, 2));
    float sum = 0.f;
    #pragma unroll
    for (int i = 0; i < 64; i++) {
      int j = i*4 + lane;
      float e2 = __expf(srow[j] - mx);
      srow[j] = e2;
      sum += e2;
    }
    sum += __shfl_xor_sync(0xffffffffu, sum, 1);
    sum += __shfl_xor_sync(0xffffffffu, sum, 2);
    float inv = 1.f / sum;
    #pragma unroll
    for (int i = 0; i < 64; i++) srow[i*4 + lane] *= inv;
  }
  __syncthreads();

  // ---- write normalized attn (B, HEADS, HW, 256) ----
  float* aout = attn_out + ((size_t)(b*NHEADS + head)*NHW + i0)*NSS;
  #pragma unroll 4
  for (int qi = 0; qi < QT; qi++)
    aout[(size_t)qi*NSS + tid] = sS[qi*SSTR + tid];

  // ---- out = attn @ V : thread owns (d = tid&63, 16 queries) ----
  {
    const int d = tid & 63;
    const int qbase = (tid >> 6) * 16;
    float acc[16];
    #pragma unroll
    for (int t=0;t<16;t++) acc[t]=0.f;
    #pragma unroll 2
    for (int j0 = 0; j0 < NSS; j0 += 4) {
      float4 vv = *(const float4*)&sKV[d*KSTR + j0];
      #pragma unroll
      for (int t = 0; t < 16; t++) {
        float4 a = *(const float4*)&sS[(qbase+t)*SSTR + j0];
        acc[t] = fmaf(a.x,vv.x, fmaf(a.y,vv.y, fmaf(a.z,vv.z, fmaf(a.w,vv.w, acc[t]))));
      }
    }
    #pragma unroll
    for (int t=0;t<16;t++) sO[(qbase+t)*OSTR + d] = acc[t];
  }
  __syncthreads();
  // ---- coalesced write to NCHW (channel = d*4 + head) ----
  #pragma unroll
  for (int l = 0; l < 16; l++) {
    int e = l*256 + tid;
    int d = e >> 6, qi = e & 63;
    av[((size_t)(b*NINNER) + d*NHEADS + head)*NHW + i0 + qi] = sO[qi*OSTR + d];
  }
}

// ======================= launch =======================
extern "C" void kernel_launch(void* const* d_in, const int* in_sizes, int n_in,
                              void* d_out, int out_size) {
  const float* x    = (const float*)d_in[0];
  const float* dw1  = (const float*)d_in[1];
  const float* pw1  = (const float*)d_in[2];
  const float* relw = (const float*)d_in[3];
  const float* relh = (const float*)d_in[4];
  const float* dw2  = (const float*)d_in[5];
  const float* pw2  = (const float*)d_in[6];

  float* out  = (float*)d_out;                          // (4,256,128,128)
  float* attn = out + (size_t)NB*NINNER*NHW;            // (4,4,16384,256)

  float *t1, *qkvb, *kpb, *vpb, *avb, *t2;
  cudaGetSymbolAddress((void**)&t1,  g_t1);
  cudaGetSymbolAddress((void**)&qkvb,g_qkv);
  cudaGetSymbolAddress((void**)&kpb, g_kp);
  cudaGetSymbolAddress((void**)&vpb, g_vp);
  cudaGetSymbolAddress((void**)&avb, g_av);
  cudaGetSymbolAddress((void**)&t2,  g_t2);

  // dsconv1
  dw3x3<<<NB*NC*NHW/256, 256>>>(x, dw1, t1);
  pw_gemm<<<dim3(NHW/128, 768/128, NB), 256>>>(pw1, t1, qkvb, 768, 256);
  // pool k, v
  pool8<<<(2*NB*NINNER*NSS)/256, 256>>>(qkvb, kpb, vpb);
  // attention (+ attn output write)
  const int smem = (64*KSTR + 64*SSTR + 64*QSTR + 2*31*RSTR + 2*64*17) * 4;
  cudaFuncSetAttribute(attn_k, cudaFuncAttributeMaxDynamicSharedMemorySize, smem);
  attn_k<<<dim3(NHW/QT, NHEADS, NB), 256, smem>>>(qkvb, kpb, vpb, relw, relh,
                                                  attn, avb);
  // dsconv2
  dw3x3<<<NB*NINNER*NHW/256, 256>>>(avb, dw2, t2);
  pw_gemm<<<dim3(NHW/128, 256/128, NB), 256>>>(pw2, t2, out, 256, 256);
}

// round 3
// speedup vs baseline: 1.4323x; 1.4323x over previous
#include <cuda_runtime.h>
#include <math.h>
#include <stdint.h>

#define NB 4
#define NC 256
#define NH 128
#define NW 128
#define NHW (NH*NW)
#define NINNER 256
#define NHEADS 4
#define NDH 64
#define NS 16
#define NSS 256
#define QT 64
#define GK 256

// -------- scratch (static device arrays; no runtime allocation) --------
__device__ float g_t1 [NB*NC*NHW];         // depthwise1 out [b][c][hw]
__device__ float g_t1t[NB*NHW*NC];         // transposed [b][hw][c]
__device__ float g_qkv[NB*3*NINNER*NHW];   // pointwise1 out (q|k|v)
__device__ float g_kp [NB*NINNER*NSS];
__device__ float g_vp [NB*NINNER*NSS];
__device__ float g_av [NB*NINNER*NHW];
__device__ float g_t2 [NB*NINNER*NHW];
__device__ float g_t2t[NB*NHW*NINNER];

__device__ __forceinline__ float rna_tf32(float x) {
  uint32_t r; asm("cvt.rna.tf32.f32 %0, %1;" : "=r"(r) : "f"(x));
  return __uint_as_float(r);
}
__device__ __forceinline__ void mma8(float* c, const uint32_t* a, const uint32_t* b) {
  asm volatile("mma.sync.aligned.m16n8k8.row.col.f32.tf32.tf32.f32 "
    "{%0,%1,%2,%3}, {%4,%5,%6,%7}, {%8,%9}, {%0,%1,%2,%3};"
    : "+f"(c[0]), "+f"(c[1]), "+f"(c[2]), "+f"(c[3])
    : "r"(a[0]), "r"(a[1]), "r"(a[2]), "r"(a[3]), "r"(b[0]), "r"(b[1]));
}

// ======================= depthwise 3x3, pad 1 =======================
__global__ void dw3x3(const float* __restrict__ in, const float* __restrict__ wt,
                      float* __restrict__ out) {
  int idx = blockIdx.x*256 + threadIdx.x;
  int x = idx & (NW-1);
  int y = (idx >> 7) & (NH-1);
  int bc = idx >> 14;
  int c = bc & (NC-1);
  const float* wp = wt + c*9;
  const float* ip = in + (size_t)bc*NHW;
  float s = 0.f;
  #pragma unroll
  for (int dy = -1; dy <= 1; dy++) {
    int yy = y + dy;
    if ((unsigned)yy >= NH) continue;
    #pragma unroll
    for (int dx = -1; dx <= 1; dx++) {
      int xx = x + dx;
      if ((unsigned)xx >= NW) continue;
      s = fmaf(ip[yy*NW+xx], wp[(dy+1)*3 + dx+1], s);
    }
  }
  out[idx] = s;
}

// ====== transpose [b][256][16384] -> [b][16384][256] ======
__global__ void __launch_bounds__(256) transp(const float* __restrict__ in,
                                              float* __restrict__ out) {
  __shared__ float t[32][33];
  int hw0 = blockIdx.x*32, c0 = blockIdx.y*32, b = blockIdx.z;
  int tx = threadIdx.x & 31, ty = threadIdx.x >> 5;
  #pragma unroll
  for (int r = 0; r < 4; r++) {
    int c = c0 + ty + r*8;
    t[ty + r*8][tx] = in[((size_t)b*256 + c)*NHW + hw0 + tx];
  }
  __syncthreads();
  #pragma unroll
  for (int r = 0; r < 4; r++) {
    int hw = hw0 + ty + r*8;
    out[((size_t)b*NHW + hw)*256 + c0 + tx] = t[tx][ty + r*8];
  }
}

// ======================= 3xTF32 mma.sync GEMM =======================
// C[b][m][n] = sum_k A[m][k] * Bt[b][n][k]; K=256, block tile 128x128, kc=32.
#define SASTR 36
__global__ void __launch_bounds__(256) mm_tf32(const float* __restrict__ A,
                                               const float* __restrict__ Bt,
                                               float* __restrict__ C, int M) {
  extern __shared__ float sm[];
  float* sAb = sm;
  float* sAs = sAb + 128*SASTR;
  float* sBb = sAs + 128*SASTR;
  float* sBs = sBb + 128*SASTR;

  const int tid = threadIdx.x;
  const int wid = tid >> 5, lane = tid & 31;
  const int wm = wid >> 2, wn = wid & 3;       // 2 x 4 warp grid
  const int g = lane >> 2, tg = lane & 3;
  const int n0 = blockIdx.x * 128;
  const int m0 = blockIdx.y * 128;
  const int bz = blockIdx.z;

  const float* Arow = A + (size_t)m0*GK;
  const float* Brow = Bt + ((size_t)bz*NHW + n0)*GK;

  float acc[4][4][4];
  #pragma unroll
  for (int i=0;i<4;i++)
    #pragma unroll
    for (int j=0;j<4;j++)
      #pragma unroll
      for (int l=0;l<4;l++) acc[i][j][l] = 0.f;

  for (int kc = 0; kc < GK; kc += 32) {
    #pragma unroll
    for (int i = 0; i < 4; i++) {
      int e = i*256 + tid;
      int r = e >> 3, c4 = e & 7;
      int so = r*SASTR + c4*4;
      float4 v = *(const float4*)(Arow + (size_t)r*GK + kc + c4*4);
      float4 vb, vs;
      vb.x = rna_tf32(v.x); vs.x = rna_tf32(v.x - vb.x);
      vb.y = rna_tf32(v.y); vs.y = rna_tf32(v.y - vb.y);
      vb.z = rna_tf32(v.z); vs.z = rna_tf32(v.z - vb.z);
      vb.w = rna_tf32(v.w); vs.w = rna_tf32(v.w - vb.w);
      *(float4*)(sAb + so) = vb;
      *(float4*)(sAs + so) = vs;
      float4 w = *(const float4*)(Brow + (size_t)r*GK + kc + c4*4);
      vb.x = rna_tf32(w.x); vs.x = rna_tf32(w.x - vb.x);
      vb.y = rna_tf32(w.y); vs.y = rna_tf32(w.y - vb.y);
      vb.z = rna_tf32(w.z); vs.z = rna_tf32(w.z - vb.z);
      vb.w = rna_tf32(w.w); vs.w = rna_tf32(w.w - vb.w);
      *(float4*)(sBb + so) = vb;
      *(float4*)(sBs + so) = vs;
    }
    __syncthreads();
    #pragma unroll
    for (int ks = 0; ks < 4; ks++) {
      int k0 = ks*8;
      uint32_t bb[4][2], bs[4][2];
      #pragma unroll
      for (int nt = 0; nt < 4; nt++) {
        int n = wn*32 + nt*8 + g;
        bb[nt][0] = __float_as_uint(sBb[n*SASTR + k0 + tg]);
        bb[nt][1] = __float_as_uint(sBb[n*SASTR + k0 + tg + 4]);
        bs[nt][0] = __float_as_uint(sBs[n*SASTR + k0 + tg]);
        bs[nt][1] = __float_as_uint(sBs[n*SASTR + k0 + tg + 4]);
      }
      #pragma unroll
      for (int mt = 0; mt < 4; mt++) {
        int m = wm*64 + mt*16 + g;
        uint32_t ab[4], as_[4];
        ab[0] = __float_as_uint(sAb[m*SASTR + k0 + tg]);
        ab[1] = __float_as_uint(sAb[(m+8)*SASTR + k0 + tg]);
        ab[2] = __float_as_uint(sAb[m*SASTR + k0 + tg + 4]);
        ab[3] = __float_as_uint(sAb[(m+8)*SASTR + k0 + tg + 4]);
        as_[0] = __float_as_uint(sAs[m*SASTR + k0 + tg]);
        as_[1] = __float_as_uint(sAs[(m+8)*SASTR + k0 + tg]);
        as_[2] = __float_as_uint(sAs[m*SASTR + k0 + tg + 4]);
        as_[3] = __float_as_uint(sAs[(m+8)*SASTR + k0 + tg + 4]);
        #pragma unroll
        for (int nt = 0; nt < 4; nt++) {
          mma8(acc[mt][nt], ab, bb[nt]);   // big*big
          mma8(acc[mt][nt], ab, bs[nt]);   // big*small
          mma8(acc[mt][nt], as_, bb[nt]);  // small*big
        }
      }
    }
    __syncthreads();
  }

  // epilogue: direct float2 stores
  float* Cb = C + (size_t)bz*M*NHW;
  #pragma unroll
  for (int mt = 0; mt < 4; mt++) {
    int row = m0 + wm*64 + mt*16 + g;
    #pragma unroll
    for (int nt = 0; nt < 4; nt++) {
      int col = n0 + wn*32 + nt*8 + 2*tg;
      *(float2*)(Cb + (size_t)row*NHW + col) =
          make_float2(acc[mt][nt][0], acc[mt][nt][1]);
      *(float2*)(Cb + (size_t)(row+8)*NHW + col) =
          make_float2(acc[mt][nt][2], acc[mt][nt][3]);
    }
  }
}

// ======================= 8x8 max pool of k and v =======================
__global__ void pool8(const float* __restrict__ qkv, float* __restrict__ kp,
                      float* __restrict__ vp) {
  int idx = blockIdx.x*256 + threadIdx.x;
  int which = idx >> 18;
  int r = idx & 262143;
  int ow = r & 15, oh = (r >> 4) & 15;
  int c = (r >> 8) & 255;
  int b = r >> 16;
  const float* ip = qkv + ((size_t)(b*768 + (which ? 512 : 256) + c))*NHW
                    + (oh*8)*NW + ow*8;
  float m = -1e30f;
  #pragma unroll
  for (int i=0;i<8;i++)
    #pragma unroll
    for (int j=0;j<8;j++)
      m = fmaxf(m, ip[i*NW+j]);
  if (which) vp[r] = m; else kp[r] = m;
}

// ======================= fused attention =======================
#define KSTR 260
#define VSTR 65
#define SSTR 260
#define QSTR 68
#define RSTR 68
#define OSTR 65

__global__ void __launch_bounds__(256) attn_k(
    const float* __restrict__ qkv, const float* __restrict__ kp,
    const float* __restrict__ vp, const float* __restrict__ relw,
    const float* __restrict__ relh, float* __restrict__ attn_out,
    float* __restrict__ av) {
  extern __shared__ float sm[];
  float* sKV = sm;                     // max(64*260, 256*65) = 16640 floats
  float* sS  = sKV + 64*KSTR;
  float* sQ  = sS + 64*SSTR;
  float* sRH = sQ + 64*QSTR;
  float* sRW = sRH + 31*RSTR;
  float* sGH = sRW + 31*RSTR;
  float* sGW = sGH + 64*17;
  float* sO  = sQ;

  const int tid = threadIdx.x;
  const int tile = blockIdx.x;
  const int head = blockIdx.y;
  const int b = blockIdx.z;
  const int i0 = tile*QT;
  const int hq = i0 >> 7;
  const int w0 = i0 & (NW-1);
  const int h8 = hq >> 3;

  #pragma unroll
  for (int l = 0; l < 16; l++) {
    int e = l*256 + tid;
    int d = e >> 6, qi = e & 63;
    sQ[qi*QSTR + d] = qkv[((size_t)(b*768) + d*NHEADS + head)*NHW + i0 + qi];
  }
  for (int e = tid; e < 31*64; e += 256) {
    int r = e >> 6, d = e & 63;
    sRH[r*RSTR + d] = relh[e];
    sRW[r*RSTR + d] = relw[e];
  }
  #pragma unroll
  for (int d = 0; d < 64; d++)
    sKV[d*KSTR + tid] = kp[((size_t)(b*NINNER) + d*NHEADS + head)*NSS + tid];
  __syncthreads();

  // ---- scores: thread owns key j = tid ----
  #pragma unroll 1
  for (int qc = 0; qc < QT; qc += 16) {
    float acc[16];
    #pragma unroll
    for (int t=0;t<16;t++) acc[t]=0.f;
    #pragma unroll
    for (int d0 = 0; d0 < 64; d0 += 4) {
      float k0v = sKV[(d0+0)*KSTR + tid];
      float k1v = sKV[(d0+1)*KSTR + tid];
      float k2v = sKV[(d0+2)*KSTR + tid];
      float k3v = sKV[(d0+3)*KSTR + tid];
      #pragma unroll
      for (int t=0;t<16;t++) {
        float4 qv = *(const float4*)&sQ[(qc+t)*QSTR + d0];
        acc[t] = fmaf(qv.x,k0v, fmaf(qv.y,k1v, fmaf(qv.z,k2v, fmaf(qv.w,k3v, acc[t]))));
      }
    }
    #pragma unroll
    for (int t=0;t<16;t++) sS[(qc+t)*SSTR + tid] = acc[t];
  }
  __syncthreads();

  // ---- V transposed to [j][d] (conflict-free both on store and AV read) ----
  #pragma unroll 8
  for (int d = 0; d < 64; d++)
    sKV[tid*VSTR + d] = vp[((size_t)(b*NINNER) + d*NHEADS + head)*NSS + tid];
  // ---- bias dots gh/gw ----
  #pragma unroll
  for (int it = 0; it < 8; it++) {
    int e = it*256 + tid;
    int isw = e >> 10;
    int qi = (e & 1023) >> 4;
    int kk = e & 15;
    int row = isw ? (kk - ((w0 + qi) >> 3) + NS - 1) : (kk - h8 + NS - 1);
    const float* tb = (isw ? sRW : sRH) + row*RSTR;
    const float* qr = sQ + qi*QSTR;
    float s = 0.f;
    #pragma unroll
    for (int d0 = 0; d0 < 64; d0 += 4) {
      float4 a = *(const float4*)&qr[d0];
      float4 c4 = *(const float4*)&tb[d0];
      s = fmaf(a.x,c4.x, fmaf(a.y,c4.y, fmaf(a.z,c4.z, fmaf(a.w,c4.w, s))));
    }
    if (isw) sGW[qi*17 + kk] = s; else sGH[qi*17 + kk] = s;
  }
  __syncthreads();

  // ---- bias + scale + softmax (4 threads / query) ----
  {
    const int q = tid >> 2, lane = tid & 3;
    float* srow = sS + q*SSTR;
    const float* ghr = sGH + q*17;
    const float* gwr = sGW + q*17;
    float mx = -1e30f;
    #pragma unroll
    for (int i = 0; i < 64; i++) {
      int j = i*4 + lane;
      float s = (srow[j] + ghr[j >> 4] + gwr[j & 15]) * 0.125f;
      srow[j] = s;
      mx = fmaxf(mx, s);
    }
    mx = fmaxf(mx, __shfl_xor_sync(0xffffffffu, mx, 1));
    mx = fmaxf(mx, __shfl_xor_sync(0xffffffffu, mx, 2));
    float sum = 0.f;
    #pragma unroll
    for (int i = 0; i < 64; i++) {
      int j = i*4 + lane;
      float e2 = __expf(srow[j] - mx);
      srow[j] = e2;
      sum += e2;
    }
    sum += __shfl_xor_sync(0xffffffffu, sum, 1);
    sum += __shfl_xor_sync(0xffffffffu, sum, 2);
    float inv = 1.f / sum;
    #pragma unroll
    for (int i = 0; i < 64; i++) srow[i*4 + lane] *= inv;
  }
  __syncthreads();

  float* aout = attn_out + ((size_t)(b*NHEADS + head)*NHW + i0)*NSS;
  #pragma unroll 4
  for (int qi = 0; qi < QT; qi++)
    aout[(size_t)qi*NSS + tid] = sS[qi*SSTR + tid];

  // ---- out = attn @ V ----
  {
    const int d = tid & 63;
    const int qbase = (tid >> 6) * 16;
    float acc[16];
    #pragma unroll
    for (int t=0;t<16;t++) acc[t]=0.f;
    #pragma unroll 4
    for (int j0 = 0; j0 < NSS; j0 += 4) {
      float v0 = sKV[(j0+0)*VSTR + d];
      float v1 = sKV[(j0+1)*VSTR + d];
      float v2 = sKV[(j0+2)*VSTR + d];
      float v3 = sKV[(j0+3)*VSTR + d];
      #pragma unroll
      for (int t = 0; t < 16; t++) {
        float4 p = *(const float4*)&sS[(qbase+t)*SSTR + j0];
        acc[t] = fmaf(p.x,v0, fmaf(p.y,v1, fmaf(p.z,v2, fmaf(p.w,v3, acc[t]))));
      }
    }
    #pragma unroll
    for (int t=0;t<16;t++) sO[(qbase+t)*OSTR + d] = acc[t];
  }
  __syncthreads();
  #pragma unroll
  for (int l = 0; l < 16; l++) {
    int e = l*256 + tid;
    int d = e >> 6, qi = e & 63;
    av[((size_t)(b*NINNER) + d*NHEADS + head)*NHW + i0 + qi] = sO[qi*OSTR + d];
  }
}

// ======================= launch =======================
extern "C" void kernel_launch(void* const* d_in, const int* in_sizes, int n_in,
                              void* d_out, int out_size) {
  const float* x    = (const float*)d_in[0];
  const float* dw1  = (const float*)d_in[1];
  const float* pw1  = (const float*)d_in[2];
  const float* relw = (const float*)d_in[3];
  const float* relh = (const float*)d_in[4];
  const float* dw2  = (const float*)d_in[5];
  const float* pw2  = (const float*)d_in[6];

  float* out  = (float*)d_out;
  float* attn = out + (size_t)NB*NINNER*NHW;

  float *t1, *t1t, *qkvb, *kpb, *vpb, *avb, *t2, *t2t;
  cudaGetSymbolAddress((void**)&t1,  g_t1);
  cudaGetSymbolAddress((void**)&t1t, g_t1t);
  cudaGetSymbolAddress((void**)&qkvb,g_qkv);
  cudaGetSymbolAddress((void**)&kpb, g_kp);
  cudaGetSymbolAddress((void**)&vpb, g_vp);
  cudaGetSymbolAddress((void**)&avb, g_av);
  cudaGetSymbolAddress((void**)&t2,  g_t2);
  cudaGetSymbolAddress((void**)&t2t, g_t2t);

  const int mm_smem = 4*128*SASTR*4;   // 73728 B
  cudaFuncSetAttribute(mm_tf32, cudaFuncAttributeMaxDynamicSharedMemorySize, mm_smem);
  const int at_smem = (64*KSTR + 64*SSTR + 64*QSTR + 2*31*RSTR + 2*64*17) * 4;
  cudaFuncSetAttribute(attn_k, cudaFuncAttributeMaxDynamicSharedMemorySize, at_smem);

  dw3x3<<<NB*NC*NHW/256, 256>>>(x, dw1, t1);
  transp<<<dim3(NHW/32, NC/32, NB), 256>>>(t1, t1t);
  mm_tf32<<<dim3(NHW/128, 768/128, NB), 256, mm_smem>>>(pw1, t1t, qkvb, 768);
  pool8<<<(2*NB*NINNER*NSS)/256, 256>>>(qkvb, kpb, vpb);
  attn_k<<<dim3(NHW/QT, NHEADS, NB), 256, at_smem>>>(qkvb, kpb, vpb, relw, relh,
                                                     attn, avb);
  dw3x3<<<NB*NINNER*NHW/256, 256>>>(avb, dw2, t2);
  transp<<<dim3(NHW/32, NINNER/32, NB), 256>>>(t2, t2t);
  mm_tf32<<<dim3(NHW/128, 256/128, NB), 256, mm_smem>>>(pw2, t2t, out, 256);
}

// round 4
// speedup vs baseline: 1.7536x; 1.2243x over previous
#include <cuda_runtime.h>
#include <math.h>
#include <stdint.h>

#define NB 4
#define NC 256
#define NH 128
#define NW 128
#define NHW (NH*NW)
#define NINNER 256
#define NHEADS 4
#define NDH 64
#define NS 16
#define NSS 256
#define QT 64
#define GK 256

// -------- scratch --------
__device__ float g_t1t[NB*NHW*NC];         // transposed dw1 out [b][hw][c]
__device__ float g_qkv[NB*3*NINNER*NHW];   // pointwise1 out (q|k|v)
__device__ float g_kp [NB*NINNER*NSS];
__device__ float g_vp [NB*NINNER*NSS];
__device__ float g_av [NB*NINNER*NHW];
__device__ float g_t2t[NB*NHW*NINNER];     // transposed dw2 out

__device__ __forceinline__ float rna_tf32(float x) {
  uint32_t r; asm("cvt.rna.tf32.f32 %0, %1;" : "=r"(r) : "f"(x));
  return __uint_as_float(r);
}
__device__ __forceinline__ void split2(float x, uint32_t& b, uint32_t& s) {
  float xb = rna_tf32(x);
  b = __float_as_uint(xb);
  s = __float_as_uint(rna_tf32(x - xb));
}
__device__ __forceinline__ void mma8(float* c, const uint32_t* a, const uint32_t* b) {
  asm volatile("mma.sync.aligned.m16n8k8.row.col.f32.tf32.tf32.f32 "
    "{%0,%1,%2,%3}, {%4,%5,%6,%7}, {%8,%9}, {%0,%1,%2,%3};"
    : "+f"(c[0]), "+f"(c[1]), "+f"(c[2]), "+f"(c[3])
    : "r"(a[0]), "r"(a[1]), "r"(a[2]), "r"(a[3]), "r"(b[0]), "r"(b[1]));
}

// ============== fused depthwise 3x3 (pad 1) + transpose, C = 256 ==============
__global__ void __launch_bounds__(256) dw_t(const float* __restrict__ in,
                                            const float* __restrict__ wt,
                                            float* __restrict__ out) {
  __shared__ float t[32][33];
  int hw0 = blockIdx.x*32, c0 = blockIdx.y*32, b = blockIdx.z;
  int tx = threadIdx.x & 31, ty = threadIdx.x >> 5;
  int x = (hw0 + tx) & (NW-1), y = (hw0 + tx) >> 7;
  #pragma unroll
  for (int r = 0; r < 4; r++) {
    int c = c0 + ty + r*8;
    const float* wp = wt + c*9;
    const float* ip = in + ((size_t)b*256 + c)*NHW;
    float s = 0.f;
    #pragma unroll
    for (int dy = -1; dy <= 1; dy++) {
      int yy = y + dy;
      if ((unsigned)yy >= NH) continue;
      #pragma unroll
      for (int dx = -1; dx <= 1; dx++) {
        int xx = x + dx;
        if ((unsigned)xx >= NW) continue;
        s = fmaf(ip[yy*NW+xx], wp[(dy+1)*3 + dx+1], s);
      }
    }
    t[ty + r*8][tx] = s;
  }
  __syncthreads();
  #pragma unroll
  for (int r = 0; r < 4; r++) {
    int hw = hw0 + ty + r*8;
    out[((size_t)b*NHW + hw)*256 + c0 + tx] = t[tx][ty + r*8];
  }
}

// ======================= 3xTF32 mma.sync GEMM =======================
#define SASTR 36
__global__ void __launch_bounds__(256) mm_tf32(const float* __restrict__ A,
                                               const float* __restrict__ Bt,
                                               float* __restrict__ C, int M) {
  extern __shared__ float sm[];
  float* sAb = sm;
  float* sAs = sAb + 128*SASTR;
  float* sBb = sAs + 128*SASTR;
  float* sBs = sBb + 128*SASTR;

  const int tid = threadIdx.x;
  const int wid = tid >> 5, lane = tid & 31;
  const int wm = wid >> 2, wn = wid & 3;
  const int g = lane >> 2, tg = lane & 3;
  const int n0 = blockIdx.x * 128;
  const int m0 = blockIdx.y * 128;
  const int bz = blockIdx.z;

  const float* Arow = A + (size_t)m0*GK;
  const float* Brow = Bt + ((size_t)bz*NHW + n0)*GK;

  float acc[4][4][4];
  #pragma unroll
  for (int i=0;i<4;i++)
    #pragma unroll
    for (int j=0;j<4;j++)
      #pragma unroll
      for (int l=0;l<4;l++) acc[i][j][l] = 0.f;

  for (int kc = 0; kc < GK; kc += 32) {
    #pragma unroll
    for (int i = 0; i < 4; i++) {
      int e = i*256 + tid;
      int r = e >> 3, c4 = e & 7;
      int so = r*SASTR + c4*4;
      float4 v = *(const float4*)(Arow + (size_t)r*GK + kc + c4*4);
      float4 vb, vs;
      vb.x = rna_tf32(v.x); vs.x = rna_tf32(v.x - vb.x);
      vb.y = rna_tf32(v.y); vs.y = rna_tf32(v.y - vb.y);
      vb.z = rna_tf32(v.z); vs.z = rna_tf32(v.z - vb.z);
      vb.w = rna_tf32(v.w); vs.w = rna_tf32(v.w - vb.w);
      *(float4*)(sAb + so) = vb;
      *(float4*)(sAs + so) = vs;
      float4 w = *(const float4*)(Brow + (size_t)r*GK + kc + c4*4);
      vb.x = rna_tf32(w.x); vs.x = rna_tf32(w.x - vb.x);
      vb.y = rna_tf32(w.y); vs.y = rna_tf32(w.y - vb.y);
      vb.z = rna_tf32(w.z); vs.z = rna_tf32(w.z - vb.z);
      vb.w = rna_tf32(w.w); vs.w = rna_tf32(w.w - vb.w);
      *(float4*)(sBb + so) = vb;
      *(float4*)(sBs + so) = vs;
    }
    __syncthreads();
    #pragma unroll
    for (int ks = 0; ks < 4; ks++) {
      int k0 = ks*8;
      uint32_t bb[4][2], bs[4][2];
      #pragma unroll
      for (int nt = 0; nt < 4; nt++) {
        int n = wn*32 + nt*8 + g;
        bb[nt][0] = __float_as_uint(sBb[n*SASTR + k0 + tg]);
        bb[nt][1] = __float_as_uint(sBb[n*SASTR + k0 + tg + 4]);
        bs[nt][0] = __float_as_uint(sBs[n*SASTR + k0 + tg]);
        bs[nt][1] = __float_as_uint(sBs[n*SASTR + k0 + tg + 4]);
      }
      #pragma unroll
      for (int mt = 0; mt < 4; mt++) {
        int m = wm*64 + mt*16 + g;
        uint32_t ab[4], as_[4];
        ab[0] = __float_as_uint(sAb[m*SASTR + k0 + tg]);
        ab[1] = __float_as_uint(sAb[(m+8)*SASTR + k0 + tg]);
        ab[2] = __float_as_uint(sAb[m*SASTR + k0 + tg + 4]);
        ab[3] = __float_as_uint(sAb[(m+8)*SASTR + k0 + tg + 4]);
        as_[0] = __float_as_uint(sAs[m*SASTR + k0 + tg]);
        as_[1] = __float_as_uint(sAs[(m+8)*SASTR + k0 + tg]);
        as_[2] = __float_as_uint(sAs[m*SASTR + k0 + tg + 4]);
        as_[3] = __float_as_uint(sAs[(m+8)*SASTR + k0 + tg + 4]);
        #pragma unroll
        for (int nt = 0; nt < 4; nt++) {
          mma8(acc[mt][nt], ab, bb[nt]);
          mma8(acc[mt][nt], ab, bs[nt]);
          mma8(acc[mt][nt], as_, bb[nt]);
        }
      }
    }
    __syncthreads();
  }

  float* Cb = C + (size_t)bz*M*NHW;
  #pragma unroll
  for (int mt = 0; mt < 4; mt++) {
    int row = m0 + wm*64 + mt*16 + g;
    #pragma unroll
    for (int nt = 0; nt < 4; nt++) {
      int col = n0 + wn*32 + nt*8 + 2*tg;
      *(float2*)(Cb + (size_t)row*NHW + col) =
          make_float2(acc[mt][nt][0], acc[mt][nt][1]);
      *(float2*)(Cb + (size_t)(row+8)*NHW + col) =
          make_float2(acc[mt][nt][2], acc[mt][nt][3]);
    }
  }
}

// ======================= 8x8 max pool of k and v =======================
__global__ void pool8(const float* __restrict__ qkv, float* __restrict__ kp,
                      float* __restrict__ vp) {
  int idx = blockIdx.x*256 + threadIdx.x;
  int which = idx >> 18;
  int r = idx & 262143;
  int ow = r & 15, oh = (r >> 4) & 15;
  int c = (r >> 8) & 255;
  int b = r >> 16;
  const float* ip = qkv + ((size_t)(b*768 + (which ? 512 : 256) + c))*NHW
                    + (oh*8)*NW + ow*8;
  float m = -1e30f;
  #pragma unroll
  for (int i=0;i<8;i++)
    #pragma unroll
    for (int j=0;j<8;j++)
      m = fmaxf(m, ip[i*NW+j]);
  if (which) vp[r] = m; else kp[r] = m;
}

// ======================= fused tensor-core attention =======================
// smem: sS [64][260] | sKV (K:[256][68] then V:[64][260]) | sQ [64][68]
//       sR [64][68] | sL [64][68]
#define SSTR 260
#define KSTR 68
#define VSTR 260
#define QSTR 68
#define RSTR 68
#define LSTR 68
#define OSTR 66

__global__ void __launch_bounds__(256) attn_k(
    const float* __restrict__ qkv, const float* __restrict__ kp,
    const float* __restrict__ vp, const float* __restrict__ relw,
    const float* __restrict__ relh, float* __restrict__ attn_out,
    float* __restrict__ av) {
  extern __shared__ float sm[];
  float* sS  = sm;                    // 16640
  float* sKV = sS + 64*SSTR;          // 17408
  float* sQ  = sKV + 17408;           // 4352
  float* sR  = sQ + 64*QSTR;          // 4352
  float* sL  = sR + 64*RSTR;          // 4352
  float* sO  = sQ;                    // reuse (64*66 = 4224 <= 4352)

  const int tid = threadIdx.x;
  const int wid = tid >> 5, lane = tid & 31;
  const int g = lane >> 2, tg = lane & 3;
  const int head = blockIdx.y;
  const int b = blockIdx.z;
  const int i0 = blockIdx.x*QT;
  const int hq = i0 >> 7;             // all 64 queries share this row
  const int w0 = i0 & (NW-1);
  const int h8 = hq >> 3;

  // ---- load Q [qi][d] ----
  #pragma unroll
  for (int l = 0; l < 16; l++) {
    int e = l*256 + tid;
    int d = e >> 6, qi = e & 63;
    sQ[qi*QSTR + d] = qkv[((size_t)(b*768) + d*NHEADS + head)*NHW + i0 + qi];
  }
  // ---- rel tables padded to 64 rows: 0..30 = relh, 32..62 = relw ----
  #pragma unroll
  for (int l = 0; l < 16; l++) {
    int e = l*256 + tid;
    int n = e >> 6, d = e & 63;
    float v = 0.f;
    if (n < 31) v = relh[n*64 + d];
    else if (n >= 32 && n < 63) v = relw[(n-32)*64 + d];
    sR[n*RSTR + d] = v;
  }
  // ---- load K as [j][d] ----
  #pragma unroll 8
  for (int d = 0; d < 64; d++)
    sKV[tid*KSTR + d] = kp[((size_t)(b*NINNER) + d*NHEADS + head)*NSS + tid];
  __syncthreads();

  // ================= QK scores (3xTF32 mma) =================
  {
    const int n0w = wid*32;
    float acc[4][4][4];
    #pragma unroll
    for (int i=0;i<4;i++)
      #pragma unroll
      for (int j=0;j<4;j++)
        #pragma unroll
        for (int l=0;l<4;l++) acc[i][j][l]=0.f;
    #pragma unroll
    for (int ks = 0; ks < 8; ks++) {
      int k0 = ks*8;
      uint32_t bb[4][2], bs[4][2];
      #pragma unroll
      for (int nt = 0; nt < 4; nt++) {
        int j = n0w + nt*8 + g;
        split2(sKV[j*KSTR + k0 + tg],     bb[nt][0], bs[nt][0]);
        split2(sKV[j*KSTR + k0 + tg + 4], bb[nt][1], bs[nt][1]);
      }
      #pragma unroll
      for (int mt = 0; mt < 4; mt++) {
        int q = mt*16 + g;
        uint32_t ab[4], as_[4];
        split2(sQ[q*QSTR + k0 + tg],         ab[0], as_[0]);
        split2(sQ[(q+8)*QSTR + k0 + tg],     ab[1], as_[1]);
        split2(sQ[q*QSTR + k0 + tg + 4],     ab[2], as_[2]);
        split2(sQ[(q+8)*QSTR + k0 + tg + 4], ab[3], as_[3]);
        #pragma unroll
        for (int nt = 0; nt < 4; nt++) {
          mma8(acc[mt][nt], ab,  bb[nt]);
          mma8(acc[mt][nt], ab,  bs[nt]);
          mma8(acc[mt][nt], as_, bb[nt]);
        }
      }
    }
    #pragma unroll
    for (int mt = 0; mt < 4; mt++) {
      int q = mt*16 + g;
      #pragma unroll
      for (int nt = 0; nt < 4; nt++) {
        int col = n0w + nt*8 + 2*tg;
        *(float2*)&sS[q*SSTR + col]     = make_float2(acc[mt][nt][0], acc[mt][nt][1]);
        *(float2*)&sS[(q+8)*SSTR + col] = make_float2(acc[mt][nt][2], acc[mt][nt][3]);
      }
    }
  }
  // ================= bias logits (64x64x64, warp = 8 cols) =================
  {
    float acc2[4][4];
    #pragma unroll
    for (int i=0;i<4;i++)
      #pragma unroll
      for (int l=0;l<4;l++) acc2[i][l]=0.f;
    #pragma unroll
    for (int ks = 0; ks < 8; ks++) {
      int k0 = ks*8;
      uint32_t bb[2], bs[2];
      int n = wid*8 + g;
      split2(sR[n*RSTR + k0 + tg],     bb[0], bs[0]);
      split2(sR[n*RSTR + k0 + tg + 4], bb[1], bs[1]);
      #pragma unroll
      for (int mt = 0; mt < 4; mt++) {
        int q = mt*16 + g;
        uint32_t ab[4], as_[4];
        split2(sQ[q*QSTR + k0 + tg],         ab[0], as_[0]);
        split2(sQ[(q+8)*QSTR + k0 + tg],     ab[1], as_[1]);
        split2(sQ[q*QSTR + k0 + tg + 4],     ab[2], as_[2]);
        split2(sQ[(q+8)*QSTR + k0 + tg + 4], ab[3], as_[3]);
        mma8(acc2[mt], ab,  bb);
        mma8(acc2[mt], ab,  bs);
        mma8(acc2[mt], as_, bb);
      }
    }
    #pragma unroll
    for (int mt = 0; mt < 4; mt++) {
      int q = mt*16 + g;
      int col = wid*8 + 2*tg;
      *(float2*)&sL[q*LSTR + col]     = make_float2(acc2[mt][0], acc2[mt][1]);
      *(float2*)&sL[(q+8)*LSTR + col] = make_float2(acc2[mt][2], acc2[mt][3]);
    }
  }
  __syncthreads();

  // ---- load V as [d][j] (overwrites K region) ----
  #pragma unroll 8
  for (int d = 0; d < 64; d++)
    sKV[d*VSTR + tid] = vp[((size_t)(b*NINNER) + d*NHEADS + head)*NSS + tid];

  // ---- bias + scale + softmax: 4 threads per query ----
  {
    const int q = tid >> 2, lane4 = tid & 3;
    float* srow = sS + q*SSTR;
    const float* lrow = sL + q*LSTR;
    const int w8 = (w0 + q) >> 3;
    float mx = -1e30f;
    #pragma unroll
    for (int i = 0; i < 64; i++) {
      int j = i*4 + lane4;
      int kh = j >> 4, kw = j & 15;
      float s = (srow[j] + lrow[kh - h8 + 15] + lrow[32 + kw - w8 + 15]) * 0.125f;
      srow[j] = s;
      mx = fmaxf(mx, s);
    }
    mx = fmaxf(mx, __shfl_xor_sync(0xffffffffu, mx, 1));
    mx = fmaxf(mx, __shfl_xor_sync(0xffffffffu, mx, 2));
    float sum = 0.f;
    #pragma unroll
    for (int i = 0; i < 64; i++) {
      int j = i*4 + lane4;
      float e2 = __expf(srow[j] - mx);
      srow[j] = e2;
      sum += e2;
    }
    sum += __shfl_xor_sync(0xffffffffu, sum, 1);
    sum += __shfl_xor_sync(0xffffffffu, sum, 2);
    float inv = 1.f / sum;
    #pragma unroll
    for (int i = 0; i < 64; i++) srow[i*4 + lane4] *= inv;
  }
  __syncthreads();

  // ---- write normalized attn ----
  float* aout = attn_out + ((size_t)(b*NHEADS + head)*NHW + i0)*NSS;
  #pragma unroll 4
  for (int qi = 0; qi < QT; qi++)
    aout[(size_t)qi*NSS + tid] = sS[qi*SSTR + tid];

  // ================= AV (64x64x256, 3xTF32 mma) =================
  {
    const int wm = wid >> 1, wn = wid & 1;
    float acc3[4][4];
    #pragma unroll
    for (int i=0;i<4;i++)
      #pragma unroll
      for (int l=0;l<4;l++) acc3[i][l]=0.f;
    #pragma unroll 8
    for (int ks = 0; ks < 32; ks++) {
      int k0 = ks*8;
      int q = wm*16 + g;
      uint32_t ab[4], as_[4];
      split2(sS[q*SSTR + k0 + tg],         ab[0], as_[0]);
      split2(sS[(q+8)*SSTR + k0 + tg],     ab[1], as_[1]);
      split2(sS[q*SSTR + k0 + tg + 4],     ab[2], as_[2]);
      split2(sS[(q+8)*SSTR + k0 + tg + 4], ab[3], as_[3]);
      #pragma unroll
      for (int nt = 0; nt < 4; nt++) {
        int d = wn*32 + nt*8 + g;
        uint32_t bb[2], bs[2];
        split2(sKV[d*VSTR + k0 + tg],     bb[0], bs[0]);
        split2(sKV[d*VSTR + k0 + tg + 4], bb[1], bs[1]);
        mma8(acc3[nt], ab,  bb);
        mma8(acc3[nt], ab,  bs);
        mma8(acc3[nt], as_, bb);
      }
    }
    int q = wm*16 + g;
    #pragma unroll
    for (int nt = 0; nt < 4; nt++) {
      int col = wn*32 + nt*8 + 2*tg;
      *(float2*)&sO[q*OSTR + col]     = make_float2(acc3[nt][0], acc3[nt][1]);
      *(float2*)&sO[(q+8)*OSTR + col] = make_float2(acc3[nt][2], acc3[nt][3]);
    }
  }
  __syncthreads();
  // ---- coalesced write to NCHW (channel = d*4 + head) ----
  #pragma unroll
  for (int l = 0; l < 16; l++) {
    int e = l*256 + tid;
    int d = e >> 6, qi = e & 63;
    av[((size_t)(b*NINNER) + d*NHEADS + head)*NHW + i0 + qi] = sO[qi*OSTR + d];
  }
}

// ======================= launch =======================
extern "C" void kernel_launch(void* const* d_in, const int* in_sizes, int n_in,
                              void* d_out, int out_size) {
  const float* x    = (const float*)d_in[0];
  const float* dw1  = (const float*)d_in[1];
  const float* pw1  = (const float*)d_in[2];
  const float* relw = (const float*)d_in[3];
  const float* relh = (const float*)d_in[4];
  const float* dw2  = (const float*)d_in[5];
  const float* pw2  = (const float*)d_in[6];

  float* out  = (float*)d_out;
  float* attn = out + (size_t)NB*NINNER*NHW;

  float *t1t, *qkvb, *kpb, *vpb, *avb, *t2t;
  cudaGetSymbolAddress((void**)&t1t, g_t1t);
  cudaGetSymbolAddress((void**)&qkvb,g_qkv);
  cudaGetSymbolAddress((void**)&kpb, g_kp);
  cudaGetSymbolAddress((void**)&vpb, g_vp);
  cudaGetSymbolAddress((void**)&avb, g_av);
  cudaGetSymbolAddress((void**)&t2t, g_t2t);

  const int mm_smem = 4*128*SASTR*4;   // 73728 B
  cudaFuncSetAttribute(mm_tf32, cudaFuncAttributeMaxDynamicSharedMemorySize, mm_smem);
  const int at_smem = (64*SSTR + 17408 + 64*QSTR + 64*RSTR + 64*LSTR) * 4; // 188416 B
  cudaFuncSetAttribute(attn_k, cudaFuncAttributeMaxDynamicSharedMemorySize, at_smem);

  // dsconv1 (fused dw+transpose) -> tensor GEMM
  dw_t<<<dim3(NHW/32, 8, NB), 256>>>(x, dw1, t1t);
  mm_tf32<<<dim3(NHW/128, 768/128, NB), 256, mm_smem>>>(pw1, t1t, qkvb, 768);
  // pool k, v
  pool8<<<(2*NB*NINNER*NSS)/256, 256>>>(qkvb, kpb, vpb);
  // fused tensor-core attention
  attn_k<<<dim3(NHW/QT, NHEADS, NB), 256, at_smem>>>(qkvb, kpb, vpb, relw, relh,
                                                     attn, avb);
  // dsconv2
  dw_t<<<dim3(NHW/32, 8, NB), 256>>>(avb, dw2, t2t);
  mm_tf32<<<dim3(NHW/128, 256/128, NB), 256, mm_smem>>>(pw2, t2t, out, 256);
}

// round 7
// speedup vs baseline: 1.7910x; 1.0213x over previous
#include <cuda_runtime.h>
#include <math.h>
#include <stdint.h>

#define NB 4
#define NC 256
#define NH 128
#define NW 128
#define NHW (NH*NW)
#define NINNER 256
#define NHEADS 4
#define NDH 64
#define NS 16
#define NSS 256
#define QT 64
#define GK 256

// -------- scratch --------
__device__ float g_t1t[NB*NHW*NC];
__device__ float g_qkv[NB*3*NINNER*NHW];
__device__ float g_kp [NB*NINNER*NSS];
__device__ float g_vp [NB*NINNER*NSS];
__device__ float g_av [NB*NINNER*NHW];
__device__ float g_t2t[NB*NHW*NINNER];

__device__ __forceinline__ float rna_tf32(float x) {
  uint32_t r; asm("cvt.rna.tf32.f32 %0, %1;" : "=r"(r) : "f"(x));
  return __uint_as_float(r);
}
__device__ __forceinline__ void split2(float x, uint32_t& b, uint32_t& s) {
  float xb = rna_tf32(x);
  b = __float_as_uint(xb);
  s = __float_as_uint(rna_tf32(x - xb));
}
__device__ __forceinline__ void mma8(float* c, const uint32_t* a, const uint32_t* b) {
  asm volatile("mma.sync.aligned.m16n8k8.row.col.f32.tf32.tf32.f32 "
    "{%0,%1,%2,%3}, {%4,%5,%6,%7}, {%8,%9}, {%0,%1,%2,%3};"
    : "+f"(c[0]), "+f"(c[1]), "+f"(c[2]), "+f"(c[3])
    : "r"(a[0]), "r"(a[1]), "r"(a[2]), "r"(a[3]), "r"(b[0]), "r"(b[1]));
}

// ============== fused depthwise 3x3 (pad 1) + transpose ==============
__global__ void __launch_bounds__(256) dw_t(const float* __restrict__ in,
                                            const float* __restrict__ wt,
                                            float* __restrict__ out) {
  __shared__ float t[32][33];
  int hw0 = blockIdx.x*32, c0 = blockIdx.y*32, b = blockIdx.z;
  int tx = threadIdx.x & 31, ty = threadIdx.x >> 5;
  int x = (hw0 + tx) & (NW-1), y = (hw0 + tx) >> 7;
  #pragma unroll
  for (int r = 0; r < 4; r++) {
    int c = c0 + ty + r*8;
    const float* wp = wt + c*9;
    const float* ip = in + ((size_t)b*256 + c)*NHW;
    float s = 0.f;
    #pragma unroll
    for (int dy = -1; dy <= 1; dy++) {
      int yy = y + dy;
      if ((unsigned)yy >= NH) continue;
      #pragma unroll
      for (int dx = -1; dx <= 1; dx++) {
        int xx = x + dx;
        if ((unsigned)xx >= NW) continue;
        s = fmaf(ip[yy*NW+xx], wp[(dy+1)*3 + dx+1], s);
      }
    }
    t[ty + r*8][tx] = s;
  }
  __syncthreads();
  #pragma unroll
  for (int r = 0; r < 4; r++) {
    int hw = hw0 + ty + r*8;
    out[((size_t)b*NHW + hw)*256 + c0 + tx] = t[tx][ty + r*8];
  }
}

// ======================= 3xTF32 mma.sync GEMM (reg-prefetch) =======================
#define SASTR 36
__global__ void __launch_bounds__(256) mm_tf32(const float* __restrict__ A,
                                               const float* __restrict__ Bt,
                                               float* __restrict__ C, int M) {
  extern __shared__ float sm[];
  float* sAb = sm;
  float* sAs = sAb + 128*SASTR;
  float* sBb = sAs + 128*SASTR;
  float* sBs = sBb + 128*SASTR;

  const int tid = threadIdx.x;
  const int wid = tid >> 5, lane = tid & 31;
  const int wm = wid >> 2, wn = wid & 3;
  const int g = lane >> 2, tg = lane & 3;
  const int n0 = blockIdx.x * 128;
  const int m0 = blockIdx.y * 128;
  const int bz = blockIdx.z;

  const float* Arow = A + (size_t)m0*GK;
  const float* Brow = Bt + ((size_t)bz*NHW + n0)*GK;

  float acc[4][4][4];
  #pragma unroll
  for (int i=0;i<4;i++)
    #pragma unroll
    for (int j=0;j<4;j++)
      #pragma unroll
      for (int l=0;l<4;l++) acc[i][j][l] = 0.f;

  float4 pa[4], pb4[4];
  #pragma unroll
  for (int i = 0; i < 4; i++) {
    int e = i*256 + tid; int r = e >> 3, c4 = e & 7;
    pa[i]  = *(const float4*)(Arow + (size_t)r*GK + c4*4);
    pb4[i] = *(const float4*)(Brow + (size_t)r*GK + c4*4);
  }

  for (int kc8 = 0; kc8 < 8; kc8++) {
    #pragma unroll
    for (int i = 0; i < 4; i++) {
      int e = i*256 + tid; int r = e >> 3, c4 = e & 7;
      int so = r*SASTR + c4*4;
      float4 v = pa[i];
      float4 vb, vs;
      vb.x = rna_tf32(v.x); vs.x = rna_tf32(v.x - vb.x);
      vb.y = rna_tf32(v.y); vs.y = rna_tf32(v.y - vb.y);
      vb.z = rna_tf32(v.z); vs.z = rna_tf32(v.z - vb.z);
      vb.w = rna_tf32(v.w); vs.w = rna_tf32(v.w - vb.w);
      *(float4*)(sAb + so) = vb;
      *(float4*)(sAs + so) = vs;
      float4 w = pb4[i];
      vb.x = rna_tf32(w.x); vs.x = rna_tf32(w.x - vb.x);
      vb.y = rna_tf32(w.y); vs.y = rna_tf32(w.y - vb.y);
      vb.z = rna_tf32(w.z); vs.z = rna_tf32(w.z - vb.z);
      vb.w = rna_tf32(w.w); vs.w = rna_tf32(w.w - vb.w);
      *(float4*)(sBb + so) = vb;
      *(float4*)(sBs + so) = vs;
    }
    __syncthreads();
    if (kc8 < 7) {
      int kc = (kc8+1)*32;
      #pragma unroll
      for (int i = 0; i < 4; i++) {
        int e = i*256 + tid; int r = e >> 3, c4 = e & 7;
        pa[i]  = *(const float4*)(Arow + (size_t)r*GK + kc + c4*4);
        pb4[i] = *(const float4*)(Brow + (size_t)r*GK + kc + c4*4);
      }
    }
    #pragma unroll
    for (int ks = 0; ks < 4; ks++) {
      int k0 = ks*8;
      uint32_t bb[4][2], bs[4][2];
      #pragma unroll
      for (int nt = 0; nt < 4; nt++) {
        int n = wn*32 + nt*8 + g;
        bb[nt][0] = __float_as_uint(sBb[n*SASTR + k0 + tg]);
        bb[nt][1] = __float_as_uint(sBb[n*SASTR + k0 + tg + 4]);
        bs[nt][0] = __float_as_uint(sBs[n*SASTR + k0 + tg]);
        bs[nt][1] = __float_as_uint(sBs[n*SASTR + k0 + tg + 4]);
      }
      #pragma unroll
      for (int mt = 0; mt < 4; mt++) {
        int m = wm*64 + mt*16 + g;
        uint32_t ab[4], as_[4];
        ab[0] = __float_as_uint(sAb[m*SASTR + k0 + tg]);
        ab[1] = __float_as_uint(sAb[(m+8)*SASTR + k0 + tg]);
        ab[2] = __float_as_uint(sAb[m*SASTR + k0 + tg + 4]);
        ab[3] = __float_as_uint(sAb[(m+8)*SASTR + k0 + tg + 4]);
        as_[0] = __float_as_uint(sAs[m*SASTR + k0 + tg]);
        as_[1] = __float_as_uint(sAs[(m+8)*SASTR + k0 + tg]);
        as_[2] = __float_as_uint(sAs[m*SASTR + k0 + tg + 4]);
        as_[3] = __float_as_uint(sAs[(m+8)*SASTR + k0 + tg + 4]);
        #pragma unroll
        for (int nt = 0; nt < 4; nt++) {
          mma8(acc[mt][nt], ab, bb[nt]);
          mma8(acc[mt][nt], ab, bs[nt]);
          mma8(acc[mt][nt], as_, bb[nt]);
        }
      }
    }
    __syncthreads();
  }

  float* Cb = C + (size_t)bz*M*NHW;
  #pragma unroll
  for (int mt = 0; mt < 4; mt++) {
    int row = m0 + wm*64 + mt*16 + g;
    #pragma unroll
    for (int nt = 0; nt < 4; nt++) {
      int col = n0 + wn*32 + nt*8 + 2*tg;
      *(float2*)(Cb + (size_t)row*NHW + col) =
          make_float2(acc[mt][nt][0], acc[mt][nt][1]);
      *(float2*)(Cb + (size_t)(row+8)*NHW + col) =
          make_float2(acc[mt][nt][2], acc[mt][nt][3]);
    }
  }
}

// ======================= 8x8 max pool =======================
__global__ void pool8(const float* __restrict__ qkv, float* __restrict__ kp,
                      float* __restrict__ vp) {
  int idx = blockIdx.x*256 + threadIdx.x;
  int which = idx >> 18;
  int r = idx & 262143;
  int ow = r & 15, oh = (r >> 4) & 15;
  int c = (r >> 8) & 255;
  int b = r >> 16;
  const float* ip = qkv + ((size_t)(b*768 + (which ? 512 : 256) + c))*NHW
                    + (oh*8)*NW + ow*8;
  float m = -1e30f;
  #pragma unroll
  for (int i=0;i<8;i++)
    #pragma unroll
    for (int j=0;j<8;j++)
      m = fmaxf(m, ip[i*NW+j]);
  if (which) vp[r] = m; else kp[r] = m;
}

// ======================= fused tensor-core attention =======================
// smem floats: sS 16640 | big 17408 (K -> Ps) | q 8704 (Qb+Qs -> Vhalf 8448)
//              r 4352 (R -> O) | L 4352   total 51456 floats = 205824 B
#define SSTR 260
#define KSTR 68
#define QSTR 68
#define RSTR 68
#define LSTR 68
#define VHSTR 132
#define OSTR 66

__global__ void __launch_bounds__(256) attn_k(
    const float* __restrict__ qkv, const float* __restrict__ kp,
    const float* __restrict__ vp, const float* __restrict__ relw,
    const float* __restrict__ relh, float* __restrict__ attn_out,
    float* __restrict__ av) {
  extern __shared__ float sm[];
  float* sS  = sm;                 // 16640
  float* sK  = sm + 16640;         // 17408 region
  float* sPs = sK;
  float* sQb = sm + 34048;         // 4352
  float* sQs = sQb + 4352;         // 4352
  float* sVh = sQb;                // 8448 (overlays Qb+Qs)
  float* sR  = sm + 42752;         // 4352
  float* sO  = sR;
  float* sL  = sm + 47104;         // 4352

  const int tid = threadIdx.x;
  const int wid = tid >> 5, lane = tid & 31;
  const int g = lane >> 2, tg = lane & 3;
  const int head = blockIdx.y;
  const int b = blockIdx.z;
  const int i0 = blockIdx.x*QT;
  const int hq = i0 >> 7;
  const int w0 = i0 & (NW-1);
  const int h8 = hq >> 3;

  // ---- load Q, pre-split ----
  #pragma unroll
  for (int l = 0; l < 16; l++) {
    int e = l*256 + tid;
    int d = e >> 6, qi = e & 63;
    float x = qkv[((size_t)(b*768) + d*NHEADS + head)*NHW + i0 + qi];
    float xb = rna_tf32(x);
    sQb[qi*QSTR + d] = xb;
    sQs[qi*QSTR + d] = rna_tf32(x - xb);
  }
  // ---- rel tables padded to 64 rows: 0..30 = relh, 32..62 = relw ----
  #pragma unroll
  for (int l = 0; l < 16; l++) {
    int e = l*256 + tid;
    int n = e >> 6, d = e & 63;
    float v = 0.f;
    if (n < 31) v = relh[n*64 + d];
    else if (n >= 32 && n < 63) v = relw[(n-32)*64 + d];
    sR[n*RSTR + d] = v;
  }
  // ---- load K as [j][d] ----
  #pragma unroll 8
  for (int d = 0; d < 64; d++)
    sK[tid*KSTR + d] = kp[((size_t)(b*NINNER) + d*NHEADS + head)*NSS + tid];
  __syncthreads();

  // ================= QK scores =================
  {
    const int n0w = wid*32;
    float acc[4][4][4];
    #pragma unroll
    for (int i=0;i<4;i++)
      #pragma unroll
      for (int j=0;j<4;j++)
        #pragma unroll
        for (int l=0;l<4;l++) acc[i][j][l]=0.f;
    #pragma unroll
    for (int ks = 0; ks < 8; ks++) {
      int k0 = ks*8;
      uint32_t bb[4][2], bs[4][2];
      #pragma unroll
      for (int nt = 0; nt < 4; nt++) {
        int j = n0w + nt*8 + g;
        split2(sK[j*KSTR + k0 + tg],     bb[nt][0], bs[nt][0]);
        split2(sK[j*KSTR + k0 + tg + 4], bb[nt][1], bs[nt][1]);
      }
      #pragma unroll
      for (int mt = 0; mt < 4; mt++) {
        int q = mt*16 + g;
        uint32_t ab[4], as_[4];
        ab[0]  = __float_as_uint(sQb[q*QSTR + k0 + tg]);
        ab[1]  = __float_as_uint(sQb[(q+8)*QSTR + k0 + tg]);
        ab[2]  = __float_as_uint(sQb[q*QSTR + k0 + tg + 4]);
        ab[3]  = __float_as_uint(sQb[(q+8)*QSTR + k0 + tg + 4]);
        as_[0] = __float_as_uint(sQs[q*QSTR + k0 + tg]);
        as_[1] = __float_as_uint(sQs[(q+8)*QSTR + k0 + tg]);
        as_[2] = __float_as_uint(sQs[q*QSTR + k0 + tg + 4]);
        as_[3] = __float_as_uint(sQs[(q+8)*QSTR + k0 + tg + 4]);
        #pragma unroll
        for (int nt = 0; nt < 4; nt++) {
          mma8(acc[mt][nt], ab,  bb[nt]);
          mma8(acc[mt][nt], ab,  bs[nt]);
          mma8(acc[mt][nt], as_, bb[nt]);
        }
      }
    }
    #pragma unroll
    for (int mt = 0; mt < 4; mt++) {
      int q = mt*16 + g;
      #pragma unroll
      for (int nt = 0; nt < 4; nt++) {
        int col = n0w + nt*8 + 2*tg;
        *(float2*)&sS[q*SSTR + col]     = make_float2(acc[mt][nt][0], acc[mt][nt][1]);
        *(float2*)&sS[(q+8)*SSTR + col] = make_float2(acc[mt][nt][2], acc[mt][nt][3]);
      }
    }
  }
  // ================= bias logits =================
  {
    float acc2[4][4];
    #pragma unroll
    for (int i=0;i<4;i++)
      #pragma unroll
      for (int l=0;l<4;l++) acc2[i][l]=0.f;
    #pragma unroll
    for (int ks = 0; ks < 8; ks++) {
      int k0 = ks*8;
      uint32_t bb[2], bs[2];
      int n = wid*8 + g;
      split2(sR[n*RSTR + k0 + tg],     bb[0], bs[0]);
      split2(sR[n*RSTR + k0 + tg + 4], bb[1], bs[1]);
      #pragma unroll
      for (int mt = 0; mt < 4; mt++) {
        int q = mt*16 + g;
        uint32_t ab[4], as_[4];
        ab[0]  = __float_as_uint(sQb[q*QSTR + k0 + tg]);
        ab[1]  = __float_as_uint(sQb[(q+8)*QSTR + k0 + tg]);
        ab[2]  = __float_as_uint(sQb[q*QSTR + k0 + tg + 4]);
        ab[3]  = __float_as_uint(sQb[(q+8)*QSTR + k0 + tg + 4]);
        as_[0] = __float_as_uint(sQs[q*QSTR + k0 + tg]);
        as_[1] = __float_as_uint(sQs[(q+8)*QSTR + k0 + tg]);
        as_[2] = __float_as_uint(sQs[q*QSTR + k0 + tg + 4]);
        as_[3] = __float_as_uint(sQs[(q+8)*QSTR + k0 + tg + 4]);
        mma8(acc2[mt], ab,  bb);
        mma8(acc2[mt], ab,  bs);
        mma8(acc2[mt], as_, bb);
      }
    }
    #pragma unroll
    for (int mt = 0; mt < 4; mt++) {
      int q = mt*16 + g;
      int col = wid*8 + 2*tg;
      *(float2*)&sL[q*LSTR + col]     = make_float2(acc2[mt][0], acc2[mt][1]);
      *(float2*)&sL[(q+8)*LSTR + col] = make_float2(acc2[mt][2], acc2[mt][3]);
    }
  }
  __syncthreads();

  // ---- V half 1 load (j 0..127) into dead Q region ----
  #pragma unroll
  for (int it = 0; it < 32; it++) {
    int e = it*256 + tid;
    int d = e >> 7, j = e & 127;
    sVh[d*VHSTR + j] = vp[((size_t)(b*NINNER) + d*NHEADS + head)*NSS + j];
  }

  // ---- bias + scale + softmax: 4 threads per query ----
  {
    const int q = tid >> 2, lane4 = tid & 3;
    float* srow = sS + q*SSTR;
    const float* lrow = sL + q*LSTR;
    const int w8 = (w0 + q) >> 3;
    float mx = -1e30f;
    #pragma unroll
    for (int i = 0; i < 64; i++) {
      int j = i*4 + lane4;
      int kh = j >> 4, kw = j & 15;
      float s = (srow[j] + lrow[kh - h8 + 15] + lrow[32 + kw - w8 + 15]) * 0.125f;
      srow[j] = s;
      mx = fmaxf(mx, s);
    }
    mx = fmaxf(mx, __shfl_xor_sync(0xffffffffu, mx, 1));
    mx = fmaxf(mx, __shfl_xor_sync(0xffffffffu, mx, 2));
    float sum = 0.f;
    #pragma unroll
    for (int i = 0; i < 64; i++) {
      int j = i*4 + lane4;
      float e2 = __expf(srow[j] - mx);
      srow[j] = e2;
      sum += e2;
    }
    sum += __shfl_xor_sync(0xffffffffu, sum, 1);
    sum += __shfl_xor_sync(0xffffffffu, sum, 2);
    float inv = 1.f / sum;
    #pragma unroll
    for (int i = 0; i < 64; i++) srow[i*4 + lane4] *= inv;
  }
  __syncthreads();

  // ---- write attn + split P (Pb in place, Ps into dead K region) ----
  float* aout = attn_out + ((size_t)(b*NHEADS + head)*NHW + i0)*NSS;
  #pragma unroll 4
  for (int qi = 0; qi < QT; qi++) {
    float p = sS[qi*SSTR + tid];
    aout[(size_t)qi*NSS + tid] = p;
    float pb = rna_tf32(p);
    sS[qi*SSTR + tid]  = pb;
    sPs[qi*SSTR + tid] = rna_tf32(p - pb);
  }
  __syncthreads();

  // ================= AV (two j-halves) =================
  {
    const int wm = wid >> 2, wn = wid & 3;    // 2 x 4
    float acc3[2][2][4];
    #pragma unroll
    for (int i=0;i<2;i++)
      #pragma unroll
      for (int j=0;j<2;j++)
        #pragma unroll
        for (int l=0;l<4;l++) acc3[i][j][l]=0.f;

    #pragma unroll 1
    for (int half = 0; half < 2; half++) {
      if (half == 1) {
        __syncthreads();
        #pragma unroll
        for (int it = 0; it < 32; it++) {
          int e = it*256 + tid;
          int d = e >> 7, j = e & 127;
          sVh[d*VHSTR + j] = vp[((size_t)(b*NINNER) + d*NHEADS + head)*NSS + 128 + j];
        }
        __syncthreads();
      }
      const int pb0 = half*128;
      #pragma unroll 4
      for (int ks = 0; ks < 16; ks++) {
        int k0 = ks*8;
        uint32_t ab[2][4], as_[2][4];
        #pragma unroll
        for (int mt = 0; mt < 2; mt++) {
          int q = wm*32 + mt*16 + g;
          ab[mt][0]  = __float_as_uint(sS[q*SSTR + pb0 + k0 + tg]);
          ab[mt][1]  = __float_as_uint(sS[(q+8)*SSTR + pb0 + k0 + tg]);
          ab[mt][2]  = __float_as_uint(sS[q*SSTR + pb0 + k0 + tg + 4]);
          ab[mt][3]  = __float_as_uint(sS[(q+8)*SSTR + pb0 + k0 + tg + 4]);
          as_[mt][0] = __float_as_uint(sPs[q*SSTR + pb0 + k0 + tg]);
          as_[mt][1] = __float_as_uint(sPs[(q+8)*SSTR + pb0 + k0 + tg]);
          as_[mt][2] = __float_as_uint(sPs[q*SSTR + pb0 + k0 + tg + 4]);
          as_[mt][3] = __float_as_uint(sPs[(q+8)*SSTR + pb0 + k0 + tg + 4]);
        }
        uint32_t bb[2][2], bs[2][2];
        #pragma unroll
        for (int nt = 0; nt < 2; nt++) {
          int d = wn*16 + nt*8 + g;
          split2(sVh[d*VHSTR + k0 + tg],     bb[nt][0], bs[nt][0]);
          split2(sVh[d*VHSTR + k0 + tg + 4], bb[nt][1], bs[nt][1]);
        }
        #pragma unroll
        for (int mt = 0; mt < 2; mt++)
          #pragma unroll
          for (int nt = 0; nt < 2; nt++) {
            mma8(acc3[mt][nt], ab[mt],  bb[nt]);
            mma8(acc3[mt][nt], ab[mt],  bs[nt]);
            mma8(acc3[mt][nt], as_[mt], bb[nt]);
          }
      }
    }
    __syncthreads();   // sO overlays sR; all reads of sR long done
    #pragma unroll
    for (int mt = 0; mt < 2; mt++) {
      int q = wm*32 + mt*16 + g;
      #pragma unroll
      for (int nt = 0; nt < 2; nt++) {
        int col = wn*16 + nt*8 + 2*tg;
        *(float2*)&sO[q*OSTR + col]     = make_float2(acc3[mt][nt][0], acc3[mt][nt][1]);
        *(float2*)&sO[(q+8)*OSTR + col] = make_float2(acc3[mt][nt][2], acc3[mt][nt][3]);
      }
    }
  }
  __syncthreads();
  #pragma unroll
  for (int l = 0; l < 16; l++) {
    int e = l*256 + tid;
    int d = e >> 6, qi = e & 63;
    av[((size_t)(b*NINNER) + d*NHEADS + head)*NHW + i0 + qi] = sO[qi*OSTR + d];
  }
}

// ======================= launch =======================
extern "C" void kernel_launch(void* const* d_in, const int* in_sizes, int n_in,
                              void* d_out, int out_size) {
  const float* x    = (const float*)d_in[0];
  const float* dw1  = (const float*)d_in[1];
  const float* pw1  = (const float*)d_in[2];
  const float* relw = (const float*)d_in[3];
  const float* relh = (const float*)d_in[4];
  const float* dw2  = (const float*)d_in[5];
  const float* pw2  = (const float*)d_in[6];

  float* out  = (float*)d_out;
  float* attn = out + (size_t)NB*NINNER*NHW;

  float *t1t, *qkvb, *kpb, *vpb, *avb, *t2t;
  cudaGetSymbolAddress((void**)&t1t, g_t1t);
  cudaGetSymbolAddress((void**)&qkvb,g_qkv);
  cudaGetSymbolAddress((void**)&kpb, g_kp);
  cudaGetSymbolAddress((void**)&vpb, g_vp);
  cudaGetSymbolAddress((void**)&avb, g_av);
  cudaGetSymbolAddress((void**)&t2t, g_t2t);

  const int mm_smem = 4*128*SASTR*4;   // 73728 B
  cudaFuncSetAttribute(mm_tf32, cudaFuncAttributeMaxDynamicSharedMemorySize, mm_smem);
  const int at_smem = 51456*4;         // 205824 B
  cudaFuncSetAttribute(attn_k, cudaFuncAttributeMaxDynamicSharedMemorySize, at_smem);

  dw_t<<<dim3(NHW/32, 8, NB), 256>>>(x, dw1, t1t);
  mm_tf32<<<dim3(NHW/128, 768/128, NB), 256, mm_smem>>>(pw1, t1t, qkvb, 768);
  pool8<<<(2*NB*NINNER*NSS)/256, 256>>>(qkvb, kpb, vpb);
  attn_k<<<dim3(NHW/QT, NHEADS, NB), 256, at_smem>>>(qkvb, kpb, vpb, relw, relh,
                                                     attn, avb);
  dw_t<<<dim3(NHW/32, 8, NB), 256>>>(avb, dw2, t2t);
  mm_tf32<<<dim3(NHW/128, 256/128, NB), 256, mm_smem>>>(pw2, t2t, out, 256);
}

// round 9
// speedup vs baseline: 2.2101x; 1.2340x over previous
#include <cuda_runtime.h>
#include <cuda_bf16.h>
#include <math.h>
#include <stdint.h>

#define NB 4
#define NC 256
#define NH 128
#define NW 128
#define NHW (NH*NW)
#define NINNER 256
#define NHEADS 4
#define NDH 64
#define NS 16
#define NSS 256
#define QT 64
#define GK 256

// -------- scratch --------
__device__ float g_t1t[NB*NHW*NC];
__device__ float g_qkv[NB*3*NINNER*NHW];
__device__ float g_kp [NB*NINNER*NSS];
__device__ float g_vp [NB*NINNER*NSS];
__device__ float g_av [NB*NINNER*NHW];
__device__ float g_t2t[NB*NHW*NINNER];

// ---- bf16x3 helpers ----
__device__ __forceinline__ void splitpack(float x0, float x1, uint32_t& b, uint32_t& s) {
  __nv_bfloat162 hb = __floats2bfloat162_rn(x0, x1);   // .x = x0 (low half)
  uint32_t bb = *(uint32_t*)&hb;
  float b0 = __uint_as_float(bb << 16);
  float b1 = __uint_as_float(bb & 0xffff0000u);
  __nv_bfloat162 hs = __floats2bfloat162_rn(x0 - b0, x1 - b1);
  b = bb;
  s = *(uint32_t*)&hs;
}
__device__ __forceinline__ void mma16(float* c, const uint32_t* a, const uint32_t* b) {
  asm volatile("mma.sync.aligned.m16n8k16.row.col.f32.bf16.bf16.f32 "
    "{%0,%1,%2,%3}, {%4,%5,%6,%7}, {%8,%9}, {%0,%1,%2,%3};"
    : "+f"(c[0]), "+f"(c[1]), "+f"(c[2]), "+f"(c[3])
    : "r"(a[0]), "r"(a[1]), "r"(a[2]), "r"(a[3]), "r"(b[0]), "r"(b[1]));
}

// ============== fused depthwise 3x3 (pad 1) + transpose ==============
__global__ void __launch_bounds__(256) dw_t(const float* __restrict__ in,
                                            const float* __restrict__ wt,
                                            float* __restrict__ out) {
  __shared__ float t[32][33];
  int hw0 = blockIdx.x*32, c0 = blockIdx.y*32, b = blockIdx.z;
  int tx = threadIdx.x & 31, ty = threadIdx.x >> 5;
  int x = (hw0 + tx) & (NW-1), y = (hw0 + tx) >> 7;
  #pragma unroll
  for (int r = 0; r < 4; r++) {
    int c = c0 + ty + r*8;
    const float* wp = wt + c*9;
    const float* ip = in + ((size_t)b*256 + c)*NHW;
    float s = 0.f;
    #pragma unroll
    for (int dy = -1; dy <= 1; dy++) {
      int yy = y + dy;
      if ((unsigned)yy >= NH) continue;
      #pragma unroll
      for (int dx = -1; dx <= 1; dx++) {
        int xx = x + dx;
        if ((unsigned)xx >= NW) continue;
        s = fmaf(ip[yy*NW+xx], wp[(dy+1)*3 + dx+1], s);
      }
    }
    t[ty + r*8][tx] = s;
  }
  __syncthreads();
  #pragma unroll
  for (int r = 0; r < 4; r++) {
    int hw = hw0 + ty + r*8;
    out[((size_t)b*NHW + hw)*256 + c0 + tx] = t[tx][ty + r*8];
  }
}

// ======================= bf16x3 mma.sync GEMM =======================
// C[b][m][n] = sum_k A[m][k]*Bt[b][n][k]; tiles 128x128, K-chunk 32 (16 pairs).
#define GP 20
__global__ void __launch_bounds__(256, 2) mm_bf16(const float* __restrict__ A,
                                                  const float* __restrict__ Bt,
                                                  float* __restrict__ C, int M) {
  __shared__ uint32_t sh[4*128*GP];       // 40960 B
  uint32_t* sAb = sh;
  uint32_t* sAs = sh + 2560;
  uint32_t* sBb = sh + 5120;
  uint32_t* sBs = sh + 7680;

  const int tid = threadIdx.x;
  const int wid = tid >> 5, lane = tid & 31;
  const int wm = wid >> 2, wn = wid & 3;
  const int g = lane >> 2, tg = lane & 3;
  const int n0 = blockIdx.x * 128;
  const int m0 = blockIdx.y * 128;
  const int bz = blockIdx.z;

  const float* Arow = A + (size_t)m0*GK;
  const float* Brow = Bt + ((size_t)bz*NHW + n0)*GK;

  float acc[4][4][4];
  #pragma unroll
  for (int i=0;i<4;i++)
    #pragma unroll
    for (int j=0;j<4;j++)
      #pragma unroll
      for (int l=0;l<4;l++) acc[i][j][l] = 0.f;

  for (int kc = 0; kc < GK; kc += 32) {
    #pragma unroll
    for (int i = 0; i < 4; i++) {
      int e = i*256 + tid; int r = e >> 3, c4 = e & 7;
      float4 v = *(const float4*)(Arow + (size_t)r*GK + kc + c4*4);
      uint32_t b0, s0, b1, s1;
      splitpack(v.x, v.y, b0, s0);
      splitpack(v.z, v.w, b1, s1);
      *(uint2*)&sAb[r*GP + c4*2] = make_uint2(b0, b1);
      *(uint2*)&sAs[r*GP + c4*2] = make_uint2(s0, s1);
      float4 w = *(const float4*)(Brow + (size_t)r*GK + kc + c4*4);
      splitpack(w.x, w.y, b0, s0);
      splitpack(w.z, w.w, b1, s1);
      *(uint2*)&sBb[r*GP + c4*2] = make_uint2(b0, b1);
      *(uint2*)&sBs[r*GP + c4*2] = make_uint2(s0, s1);
    }
    __syncthreads();
    #pragma unroll
    for (int ks = 0; ks < 2; ks++) {
      int k0 = ks*8;
      uint32_t bb[4][2], bs[4][2];
      #pragma unroll
      for (int nt = 0; nt < 4; nt++) {
        int n = wn*32 + nt*8 + g;
        bb[nt][0] = sBb[n*GP + k0 + tg];
        bb[nt][1] = sBb[n*GP + k0 + tg + 4];
        bs[nt][0] = sBs[n*GP + k0 + tg];
        bs[nt][1] = sBs[n*GP + k0 + tg + 4];
      }
      #pragma unroll
      for (int mt = 0; mt < 4; mt++) {
        int m = wm*64 + mt*16 + g;
        uint32_t ab[4], as_[4];
        ab[0]  = sAb[m*GP + k0 + tg];
        ab[1]  = sAb[(m+8)*GP + k0 + tg];
        ab[2]  = sAb[m*GP + k0 + tg + 4];
        ab[3]  = sAb[(m+8)*GP + k0 + tg + 4];
        as_[0] = sAs[m*GP + k0 + tg];
        as_[1] = sAs[(m+8)*GP + k0 + tg];
        as_[2] = sAs[m*GP + k0 + tg + 4];
        as_[3] = sAs[(m+8)*GP + k0 + tg + 4];
        #pragma unroll
        for (int nt = 0; nt < 4; nt++) {
          mma16(acc[mt][nt], ab,  bb[nt]);
          mma16(acc[mt][nt], ab,  bs[nt]);
          mma16(acc[mt][nt], as_, bb[nt]);
        }
      }
    }
    __syncthreads();
  }

  float* Cb = C + (size_t)bz*M*NHW;
  #pragma unroll
  for (int mt = 0; mt < 4; mt++) {
    int row = m0 + wm*64 + mt*16 + g;
    #pragma unroll
    for (int nt = 0; nt < 4; nt++) {
      int col = n0 + wn*32 + nt*8 + 2*tg;
      *(float2*)(Cb + (size_t)row*NHW + col) =
          make_float2(acc[mt][nt][0], acc[mt][nt][1]);
      *(float2*)(Cb + (size_t)(row+8)*NHW + col) =
          make_float2(acc[mt][nt][2], acc[mt][nt][3]);
    }
  }
}

// ======================= 8x8 max pool =======================
__global__ void pool8(const float* __restrict__ qkv, float* __restrict__ kp,
                      float* __restrict__ vp) {
  int idx = blockIdx.x*256 + threadIdx.x;
  int which = idx >> 18;
  int r = idx & 262143;
  int ow = r & 15, oh = (r >> 4) & 15;
  int c = (r >> 8) & 255;
  int b = r >> 16;
  const float* ip = qkv + ((size_t)(b*768 + (which ? 512 : 256) + c))*NHW
                    + (oh*8)*NW + ow*8;
  float m = -1e30f;
  #pragma unroll
  for (int i=0;i<8;i++)
    #pragma unroll
    for (int j=0;j<8;j++)
      m = fmaxf(m, ip[i*NW+j]);
  if (which) vp[r] = m; else kp[r] = m;
}

// ======================= fused bf16x3 tensor-core attention =======================
// smem words (u32/f32): sS 16640 | Kb 9216 | Ks 9216 (K -> P) |
//   Qb 2304 | Qs 2304 | Rb 2304 | Rs 2304 (Q+R -> V halves) | L 4352
// total 48640 words = 194560 B
#define SSTR 260
#define KPP 36
#define QPP 36
#define RPP 36
#define PPP 132
#define VPP 68
#define LSTR 68
#define OSTR 66

__global__ void __launch_bounds__(256) attn_k(
    const float* __restrict__ qkv, const float* __restrict__ kp,
    const float* __restrict__ vp, const float* __restrict__ relw,
    const float* __restrict__ relh, float* __restrict__ attn_out,
    float* __restrict__ av) {
  extern __shared__ float smf[];
  uint32_t* smu = (uint32_t*)smf;
  float*    sS  = smf;                    // 16640 f
  uint32_t* sKb = smu + 16640;            // 9216
  uint32_t* sKs = smu + 25856;            // 9216
  uint32_t* sQb = smu + 35072;            // 2304
  uint32_t* sQs = smu + 37376;            // 2304
  uint32_t* sRb = smu + 39680;            // 2304
  uint32_t* sRs = smu + 41984;            // 2304
  float*    sL  = smf + 44288;            // 4352
  uint32_t* sPb = sKb;                    // P overlays K
  uint32_t* sPs = sKs;
  uint32_t* sVb = smu + 35072;            // V halves overlay Q+R (8704 <= 9216)
  uint32_t* sVs = smu + 39424;
  float*    sO  = smf;                    // out overlays sS

  const int tid = threadIdx.x;
  const int wid = tid >> 5, lane = tid & 31;
  const int g = lane >> 2, tg = lane & 3;
  const int head = blockIdx.y;
  const int b = blockIdx.z;
  const int i0 = blockIdx.x*QT;
  const int hq = i0 >> 7;
  const int w0 = i0 & (NW-1);
  const int h8 = hq >> 3;

  // ---- load Q, split+pack (pairs along d) ----
  #pragma unroll
  for (int l = 0; l < 8; l++) {
    int e = l*256 + tid;
    int dp = e >> 6, qi = e & 63;
    float x0 = qkv[((size_t)(b*768) + (2*dp)*NHEADS + head)*NHW + i0 + qi];
    float x1 = qkv[((size_t)(b*768) + (2*dp+1)*NHEADS + head)*NHW + i0 + qi];
    splitpack(x0, x1, sQb[qi*QPP + dp], sQs[qi*QPP + dp]);
  }
  // ---- rel tables padded to 64 rows: 0..30 relh, 32..62 relw ----
  #pragma unroll
  for (int l = 0; l < 8; l++) {
    int e = l*256 + tid;
    int dp = e >> 6, n = e & 63;
    float x0 = 0.f, x1 = 0.f;
    if (n < 31)             { x0 = relh[n*64 + 2*dp];      x1 = relh[n*64 + 2*dp + 1]; }
    else if (n >= 32 && n < 63) { x0 = relw[(n-32)*64 + 2*dp]; x1 = relw[(n-32)*64 + 2*dp + 1]; }
    splitpack(x0, x1, sRb[n*RPP + dp], sRs[n*RPP + dp]);
  }
  // ---- load K row j = tid, split+pack ----
  #pragma unroll 8
  for (int dp = 0; dp < 32; dp++) {
    float x0 = kp[((size_t)(b*NINNER) + (2*dp)*NHEADS + head)*NSS + tid];
    float x1 = kp[((size_t)(b*NINNER) + (2*dp+1)*NHEADS + head)*NSS + tid];
    splitpack(x0, x1, sKb[tid*KPP + dp], sKs[tid*KPP + dp]);
  }
  __syncthreads();

  // ================= QK scores =================
  {
    const int n0w = wid*32;
    float acc[4][4][4];
    #pragma unroll
    for (int i=0;i<4;i++)
      #pragma unroll
      for (int j=0;j<4;j++)
        #pragma unroll
        for (int l=0;l<4;l++) acc[i][j][l]=0.f;
    #pragma unroll
    for (int ks = 0; ks < 4; ks++) {
      int k0 = ks*8;
      uint32_t bb[4][2], bs[4][2];
      #pragma unroll
      for (int nt = 0; nt < 4; nt++) {
        int j = n0w + nt*8 + g;
        bb[nt][0] = sKb[j*KPP + k0 + tg];
        bb[nt][1] = sKb[j*KPP + k0 + tg + 4];
        bs[nt][0] = sKs[j*KPP + k0 + tg];
        bs[nt][1] = sKs[j*KPP + k0 + tg + 4];
      }
      #pragma unroll
      for (int mt = 0; mt < 4; mt++) {
        int q = mt*16 + g;
        uint32_t ab[4], as_[4];
        ab[0]  = sQb[q*QPP + k0 + tg];
        ab[1]  = sQb[(q+8)*QPP + k0 + tg];
        ab[2]  = sQb[q*QPP + k0 + tg + 4];
        ab[3]  = sQb[(q+8)*QPP + k0 + tg + 4];
        as_[0] = sQs[q*QPP + k0 + tg];
        as_[1] = sQs[(q+8)*QPP + k0 + tg];
        as_[2] = sQs[q*QPP + k0 + tg + 4];
        as_[3] = sQs[(q+8)*QPP + k0 + tg + 4];
        #pragma unroll
        for (int nt = 0; nt < 4; nt++) {
          mma16(acc[mt][nt], ab,  bb[nt]);
          mma16(acc[mt][nt], ab,  bs[nt]);
          mma16(acc[mt][nt], as_, bb[nt]);
        }
      }
    }
    #pragma unroll
    for (int mt = 0; mt < 4; mt++) {
      int q = mt*16 + g;
      #pragma unroll
      for (int nt = 0; nt < 4; nt++) {
        int col = n0w + nt*8 + 2*tg;
        *(float2*)&sS[q*SSTR + col]     = make_float2(acc[mt][nt][0], acc[mt][nt][1]);
        *(float2*)&sS[(q+8)*SSTR + col] = make_float2(acc[mt][nt][2], acc[mt][nt][3]);
      }
    }
  }
  // ================= bias logits =================
  {
    float acc2[4][4];
    #pragma unroll
    for (int i=0;i<4;i++)
      #pragma unroll
      for (int l=0;l<4;l++) acc2[i][l]=0.f;
    #pragma unroll
    for (int ks = 0; ks < 4; ks++) {
      int k0 = ks*8;
      int n = wid*8 + g;
      uint32_t bb[2], bs[2];
      bb[0] = sRb[n*RPP + k0 + tg];
      bb[1] = sRb[n*RPP + k0 + tg + 4];
      bs[0] = sRs[n*RPP + k0 + tg];
      bs[1] = sRs[n*RPP + k0 + tg + 4];
      #pragma unroll
      for (int mt = 0; mt < 4; mt++) {
        int q = mt*16 + g;
        uint32_t ab[4], as_[4];
        ab[0]  = sQb[q*QPP + k0 + tg];
        ab[1]  = sQb[(q+8)*QPP + k0 + tg];
        ab[2]  = sQb[q*QPP + k0 + tg + 4];
        ab[3]  = sQb[(q+8)*QPP + k0 + tg + 4];
        as_[0] = sQs[q*QPP + k0 + tg];
        as_[1] = sQs[(q+8)*QPP + k0 + tg];
        as_[2] = sQs[q*QPP + k0 + tg + 4];
        as_[3] = sQs[(q+8)*QPP + k0 + tg + 4];
        mma16(acc2[mt], ab,  bb);
        mma16(acc2[mt], ab,  bs);
        mma16(acc2[mt], as_, bb);
      }
    }
    #pragma unroll
    for (int mt = 0; mt < 4; mt++) {
      int q = mt*16 + g;
      int col = wid*8 + 2*tg;
      *(float2*)&sL[q*LSTR + col]     = make_float2(acc2[mt][0], acc2[mt][1]);
      *(float2*)&sL[(q+8)*LSTR + col] = make_float2(acc2[mt][2], acc2[mt][3]);
    }
  }
  __syncthreads();

  // ---- V half 0 (j 0..127) load+split into dead Q/R region ----
  #pragma unroll
  for (int it = 0; it < 16; it++) {
    int e = it*256 + tid;
    int d = e >> 6, jp = e & 63;
    float2 v2 = *(const float2*)&vp[((size_t)(b*NINNER) + d*NHEADS + head)*NSS + 2*jp];
    splitpack(v2.x, v2.y, sVb[d*VPP + jp], sVs[d*VPP + jp]);
  }

  // ---- bias + scale + softmax: 4 threads per query ----
  {
    const int q = tid >> 2, lane4 = tid & 3;
    float* srow = sS + q*SSTR;
    const float* lrow = sL + q*LSTR;
    const int w8 = (w0 + q) >> 3;
    float mx = -1e30f;
    #pragma unroll
    for (int i = 0; i < 64; i++) {
      int j = i*4 + lane4;
      int kh = j >> 4, kw = j & 15;
      float s = (srow[j] + lrow[kh - h8 + 15] + lrow[32 + kw - w8 + 15]) * 0.125f;
      srow[j] = s;
      mx = fmaxf(mx, s);
    }
    mx = fmaxf(mx, __shfl_xor_sync(0xffffffffu, mx, 1));
    mx = fmaxf(mx, __shfl_xor_sync(0xffffffffu, mx, 2));
    float sum = 0.f;
    #pragma unroll
    for (int i = 0; i < 64; i++) {
      int j = i*4 + lane4;
      float e2 = __expf(srow[j] - mx);
      srow[j] = e2;
      sum += e2;
    }
    sum += __shfl_xor_sync(0xffffffffu, sum, 1);
    sum += __shfl_xor_sync(0xffffffffu, sum, 2);
    float inv = 1.f / sum;
    #pragma unroll
    for (int i = 0; i < 64; i++) srow[i*4 + lane4] *= inv;
  }
  __syncthreads();

  // ---- write attn + split P packed into dead K region ----
  float* aout = attn_out + ((size_t)(b*NHEADS + head)*NHW + i0)*NSS;
  #pragma unroll 8
  for (int it = 0; it < 32; it++) {
    int e = it*256 + tid;
    int qi = e >> 7, jp = e & 127;
    float2 p2 = *(const float2*)&sS[qi*SSTR + 2*jp];
    *(float2*)&aout[(size_t)qi*NSS + 2*jp] = p2;
    splitpack(p2.x, p2.y, sPb[qi*PPP + jp], sPs[qi*PPP + jp]);
  }
  __syncthreads();

  // ================= AV (two j-halves) =================
  {
    const int wm = wid >> 2, wn = wid & 3;   // 2 x 4
    float acc3[2][2][4];
    #pragma unroll
    for (int i=0;i<2;i++)
      #pragma unroll
      for (int j=0;j<2;j++)
        #pragma unroll
        for (int l=0;l<4;l++) acc3[i][j][l]=0.f;

    #pragma unroll 1
    for (int half = 0; half < 2; half++) {
      if (half == 1) {
        __syncthreads();
        #pragma unroll
        for (int it = 0; it < 16; it++) {
          int e = it*256 + tid;
          int d = e >> 6, jp = e & 63;
          float2 v2 = *(const float2*)&vp[((size_t)(b*NINNER) + d*NHEADS + head)*NSS + 128 + 2*jp];
          splitpack(v2.x, v2.y, sVb[d*VPP + jp], sVs[d*VPP + jp]);
        }
        __syncthreads();
      }
      const int p0 = half*64;
      #pragma unroll 4
      for (int ks = 0; ks < 8; ks++) {
        int k0 = ks*8;
        uint32_t ab[2][4], as_[2][4];
        #pragma unroll
        for (int mt = 0; mt < 2; mt++) {
          int q = wm*32 + mt*16 + g;
          ab[mt][0]  = sPb[q*PPP + p0 + k0 + tg];
          ab[mt][1]  = sPb[(q+8)*PPP + p0 + k0 + tg];
          ab[mt][2]  = sPb[q*PPP + p0 + k0 + tg + 4];
          ab[mt][3]  = sPb[(q+8)*PPP + p0 + k0 + tg + 4];
          as_[mt][0] = sPs[q*PPP + p0 + k0 + tg];
          as_[mt][1] = sPs[(q+8)*PPP + p0 + k0 + tg];
          as_[mt][2] = sPs[q*PPP + p0 + k0 + tg + 4];
          as_[mt][3] = sPs[(q+8)*PPP + p0 + k0 + tg + 4];
        }
        uint32_t bb[2][2], bs[2][2];
        #pragma unroll
        for (int nt = 0; nt < 2; nt++) {
          int d = wn*16 + nt*8 + g;
          bb[nt][0] = sVb[d*VPP + k0 + tg];
          bb[nt][1] = sVb[d*VPP + k0 + tg + 4];
          bs[nt][0] = sVs[d*VPP + k0 + tg];
          bs[nt][1] = sVs[d*VPP + k0 + tg + 4];
        }
        #pragma unroll
        for (int mt = 0; mt < 2; mt++)
          #pragma unroll
          for (int nt = 0; nt < 2; nt++) {
            mma16(acc3[mt][nt], ab[mt],  bb[nt]);
            mma16(acc3[mt][nt], ab[mt],  bs[nt]);
            mma16(acc3[mt][nt], as_[mt], bb[nt]);
          }
      }
    }
    #pragma unroll
    for (int mt = 0; mt < 2; mt++) {
      int q = wm*32 + mt*16 + g;
      #pragma unroll
      for (int nt = 0; nt < 2; nt++) {
        int col = wn*16 + nt*8 + 2*tg;
        *(float2*)&sO[q*OSTR + col]     = make_float2(acc3[mt][nt][0], acc3[mt][nt][1]);
        *(float2*)&sO[(q+8)*OSTR + col] = make_float2(acc3[mt][nt][2], acc3[mt][nt][3]);
      }
    }
  }
  __syncthreads();
  #pragma unroll
  for (int l = 0; l < 16; l++) {
    int e = l*256 + tid;
    int d = e >> 6, qi = e & 63;
    av[((size_t)(b*NINNER) + d*NHEADS + head)*NHW + i0 + qi] = sO[qi*OSTR + d];
  }
}

// ======================= launch =======================
extern "C" void kernel_launch(void* const* d_in, const int* in_sizes, int n_in,
                              void* d_out, int out_size) {
  const float* x    = (const float*)d_in[0];
  const float* dw1  = (const float*)d_in[1];
  const float* pw1  = (const float*)d_in[2];
  const float* relw = (const float*)d_in[3];
  const float* relh = (const float*)d_in[4];
  const float* dw2  = (const float*)d_in[5];
  const float* pw2  = (const float*)d_in[6];

  float* out  = (float*)d_out;
  float* attn = out + (size_t)NB*NINNER*NHW;

  float *t1t, *qkvb, *kpb, *vpb, *avb, *t2t;
  cudaGetSymbolAddress((void**)&t1t, g_t1t);
  cudaGetSymbolAddress((void**)&qkvb,g_qkv);
  cudaGetSymbolAddress((void**)&kpb, g_kp);
  cudaGetSymbolAddress((void**)&vpb, g_vp);
  cudaGetSymbolAddress((void**)&avb, g_av);
  cudaGetSymbolAddress((void**)&t2t, g_t2t);

  const int at_smem = 48640*4;   // 194560 B
  cudaFuncSetAttribute(attn_k, cudaFuncAttributeMaxDynamicSharedMemorySize, at_smem);

  dw_t<<<dim3(NHW/32, 8, NB), 256>>>(x, dw1, t1t);
  mm_bf16<<<dim3(NHW/128, 768/128, NB), 256>>>(pw1, t1t, qkvb, 768);
  pool8<<<(2*NB*NINNER*NSS)/256, 256>>>(qkvb, kpb, vpb);
  attn_k<<<dim3(NHW/QT, NHEADS, NB), 256, at_smem>>>(qkvb, kpb, vpb, relw, relh,
                                                     attn, avb);
  dw_t<<<dim3(NHW/32, 8, NB), 256>>>(avb, dw2, t2t);
  mm_bf16<<<dim3(NHW/128, 256/128, NB), 256>>>(pw2, t2t, out, 256);
}